// round 1
// baseline (speedup 1.0000x reference)
#include <cuda_runtime.h>
#include <math.h>

// Problem constants
#define Bn 8
#define Ln 2048
#define Dn 1024
#define M_ALL (Bn * Ln)   // 16384

// Scratch (device globals: allocation-free rule)
__device__ float g_q[(size_t)Bn * Ln * Dn];
__device__ float g_k[(size_t)Bn * Ln * Dn];
__device__ float g_v[(size_t)Bn * Ln * Dn];
__device__ float g_ctx_scratch[(size_t)Bn * Ln * Dn];
__device__ float g_attn_scratch[(size_t)Bn * Ln * Ln];
__device__ int   g_lens[Bn];

// ---------------------------------------------------------------------------
// input_lens dtype sniffing: reference declares int64 but jax may emit int32.
// int64 little-endian view as int32 gives pairs [v, 0]; valid lens are in
// [1, Ln], so a 0 in the odd slots can only come from int64 layout.
// ---------------------------------------------------------------------------
__global__ void prep_lens_kernel(const void* lensraw) {
    if (threadIdx.x == 0 && blockIdx.x == 0) {
        const int* a32 = (const int*)lensraw;
        bool is64 = true;
        #pragma unroll
        for (int i = 0; i < 4; i++) {
            int lo = a32[2 * i], hi = a32[2 * i + 1];
            if (hi != 0 || lo < 1 || lo > Ln) { is64 = false; break; }
        }
        if (is64) {
            const long long* a64 = (const long long*)lensraw;
            for (int i = 0; i < Bn; i++) g_lens[i] = (int)a64[i];
        } else {
            for (int i = 0; i < Bn; i++) g_lens[i] = a32[i];
        }
    }
}

// ---------------------------------------------------------------------------
// NT GEMM: C[m,n] = sum_k A[m,k] * W[n,k]   (both operands K-contiguous)
// 64x64 C tile, K-tile 16, 256 threads, 4x4 register micro-tile per thread.
// ---------------------------------------------------------------------------
__global__ __launch_bounds__(256)
void gemm_nt_kernel(const float* __restrict__ A, const float* __restrict__ W,
                    float* __restrict__ C, int M, int N, int K) {
    __shared__ float As[16][68];
    __shared__ float Bs[16][68];

    const int tid  = threadIdx.x;
    const int row0 = blockIdx.y * 64;
    const int col0 = blockIdx.x * 64;
    const int ty   = tid >> 4;       // 0..15
    const int tx   = tid & 15;       // 0..15

    const int lr = tid >> 2;         // 0..63 : tile row for loads
    const int lk = (tid & 3) * 4;    // 0,4,8,12 : k sub-offset

    float acc[4][4];
    #pragma unroll
    for (int i = 0; i < 4; i++)
        #pragma unroll
        for (int j = 0; j < 4; j++) acc[i][j] = 0.0f;

    const float* Aload = A + (size_t)(row0 + lr) * K + lk;
    const float* Wload = W + (size_t)(col0 + lr) * K + lk;

    for (int kt = 0; kt < K; kt += 16) {
        float4 av = *(const float4*)(Aload + kt);
        float4 bv = *(const float4*)(Wload + kt);
        As[lk + 0][lr] = av.x; As[lk + 1][lr] = av.y;
        As[lk + 2][lr] = av.z; As[lk + 3][lr] = av.w;
        Bs[lk + 0][lr] = bv.x; Bs[lk + 1][lr] = bv.y;
        Bs[lk + 2][lr] = bv.z; Bs[lk + 3][lr] = bv.w;
        __syncthreads();

        #pragma unroll
        for (int k = 0; k < 16; k++) {
            float a[4], b[4];
            *(float4*)a = *(const float4*)&As[k][ty * 4];
            *(float4*)b = *(const float4*)&Bs[k][tx * 4];
            #pragma unroll
            for (int i = 0; i < 4; i++)
                #pragma unroll
                for (int j = 0; j < 4; j++)
                    acc[i][j] = fmaf(a[i], b[j], acc[i][j]);
        }
        __syncthreads();
    }

    #pragma unroll
    for (int i = 0; i < 4; i++) {
        float* crow = C + (size_t)(row0 + ty * 4 + i) * N + col0 + tx * 4;
        #pragma unroll
        for (int j = 0; j < 4; j++) crow[j] = acc[i][j];
    }
}

// ---------------------------------------------------------------------------
// Scores: per-batch NT GEMM scores[b] = Q[b] K[b]^T / 32, with query-row mask.
// Masked rows written as exactly -1e9 (matches reference pre-softmax values).
// ---------------------------------------------------------------------------
__global__ __launch_bounds__(256)
void scores_kernel(float* __restrict__ attn) {
    const int b = blockIdx.z;
    const float* A = g_q + (size_t)b * Ln * Dn;
    const float* W = g_k + (size_t)b * Ln * Dn;
    float* C = attn + (size_t)b * Ln * Ln;

    __shared__ float As[16][68];
    __shared__ float Bs[16][68];

    const int tid  = threadIdx.x;
    const int row0 = blockIdx.y * 64;
    const int col0 = blockIdx.x * 64;
    const int ty   = tid >> 4;
    const int tx   = tid & 15;
    const int lr   = tid >> 2;
    const int lk   = (tid & 3) * 4;

    float acc[4][4];
    #pragma unroll
    for (int i = 0; i < 4; i++)
        #pragma unroll
        for (int j = 0; j < 4; j++) acc[i][j] = 0.0f;

    const float* Aload = A + (size_t)(row0 + lr) * Dn + lk;
    const float* Wload = W + (size_t)(col0 + lr) * Dn + lk;

    for (int kt = 0; kt < Dn; kt += 16) {
        float4 av = *(const float4*)(Aload + kt);
        float4 bv = *(const float4*)(Wload + kt);
        As[lk + 0][lr] = av.x; As[lk + 1][lr] = av.y;
        As[lk + 2][lr] = av.z; As[lk + 3][lr] = av.w;
        Bs[lk + 0][lr] = bv.x; Bs[lk + 1][lr] = bv.y;
        Bs[lk + 2][lr] = bv.z; Bs[lk + 3][lr] = bv.w;
        __syncthreads();

        #pragma unroll
        for (int k = 0; k < 16; k++) {
            float a[4], bb[4];
            *(float4*)a  = *(const float4*)&As[k][ty * 4];
            *(float4*)bb = *(const float4*)&Bs[k][tx * 4];
            #pragma unroll
            for (int i = 0; i < 4; i++)
                #pragma unroll
                for (int j = 0; j < 4; j++)
                    acc[i][j] = fmaf(a[i], bb[j], acc[i][j]);
        }
        __syncthreads();
    }

    const int len = g_lens[b];
    #pragma unroll
    for (int i = 0; i < 4; i++) {
        const int q = row0 + ty * 4 + i;
        const bool valid = (q < len);
        float* crow = C + (size_t)q * Ln + col0 + tx * 4;
        #pragma unroll
        for (int j = 0; j < 4; j++)
            crow[j] = valid ? acc[i][j] * 0.03125f : -1e9f;
    }
}

// ---------------------------------------------------------------------------
// Row softmax over Ln=2048, in place. One block (256 thr) per row, 8 elems/thr.
// Fully masked rows (all -1e9) normalize to exactly 1/2048 like the reference.
// ---------------------------------------------------------------------------
__global__ __launch_bounds__(256)
void softmax_kernel(float* __restrict__ attn) {
    const size_t row = blockIdx.x;
    float* p = attn + row * Ln;
    const int t = threadIdx.x;

    float v[8];
    float m = -INFINITY;
    #pragma unroll
    for (int i = 0; i < 8; i++) {
        v[i] = p[t + i * 256];
        m = fmaxf(m, v[i]);
    }

    __shared__ float red[256];
    red[t] = m;
    __syncthreads();
    #pragma unroll
    for (int s = 128; s > 0; s >>= 1) {
        if (t < s) red[t] = fmaxf(red[t], red[t + s]);
        __syncthreads();
    }
    m = red[0];
    __syncthreads();

    float sum = 0.0f;
    #pragma unroll
    for (int i = 0; i < 8; i++) {
        v[i] = expf(v[i] - m);
        sum += v[i];
    }
    red[t] = sum;
    __syncthreads();
    #pragma unroll
    for (int s = 128; s > 0; s >>= 1) {
        if (t < s) red[t] += red[t + s];
        __syncthreads();
    }
    const float inv = 1.0f / red[0];

    #pragma unroll
    for (int i = 0; i < 8; i++)
        p[t + i * 256] = v[i] * inv;
}

// ---------------------------------------------------------------------------
// Context: per-batch NN GEMM  ctx[q,d] = sum_k attn[q,k] * V[k,d]
// ---------------------------------------------------------------------------
__global__ __launch_bounds__(256)
void ctx_kernel(const float* __restrict__ attn, float* __restrict__ ctx) {
    const int b = blockIdx.z;
    const float* A = attn + (size_t)b * Ln * Ln;
    const float* V = g_v  + (size_t)b * Ln * Dn;
    float* C = ctx + (size_t)b * Ln * Dn;

    __shared__ float As[16][68];
    __shared__ float Bs[16][68];

    const int tid  = threadIdx.x;
    const int row0 = blockIdx.y * 64;
    const int col0 = blockIdx.x * 64;
    const int ty   = tid >> 4;
    const int tx   = tid & 15;

    const int lar = tid >> 2;        // A-tile row 0..63
    const int lak = (tid & 3) * 4;   // A-tile k sub-offset
    const int lbk = tid >> 4;        // B-tile k row 0..15
    const int lbn = (tid & 15) * 4;  // B-tile col sub-offset

    float acc[4][4];
    #pragma unroll
    for (int i = 0; i < 4; i++)
        #pragma unroll
        for (int j = 0; j < 4; j++) acc[i][j] = 0.0f;

    const float* Aload = A + (size_t)(row0 + lar) * Ln + lak;

    for (int kt = 0; kt < Ln; kt += 16) {
        float4 av = *(const float4*)(Aload + kt);
        As[lak + 0][lar] = av.x; As[lak + 1][lar] = av.y;
        As[lak + 2][lar] = av.z; As[lak + 3][lar] = av.w;
        float4 bv = *(const float4*)(V + (size_t)(kt + lbk) * Dn + col0 + lbn);
        *(float4*)&Bs[lbk][lbn] = bv;
        __syncthreads();

        #pragma unroll
        for (int k = 0; k < 16; k++) {
            float a[4], bb[4];
            *(float4*)a  = *(const float4*)&As[k][ty * 4];
            *(float4*)bb = *(const float4*)&Bs[k][tx * 4];
            #pragma unroll
            for (int i = 0; i < 4; i++)
                #pragma unroll
                for (int j = 0; j < 4; j++)
                    acc[i][j] = fmaf(a[i], bb[j], acc[i][j]);
        }
        __syncthreads();
    }

    #pragma unroll
    for (int i = 0; i < 4; i++) {
        float* crow = C + (size_t)(row0 + ty * 4 + i) * Dn + col0 + tx * 4;
        #pragma unroll
        for (int j = 0; j < 4; j++) crow[j] = acc[i][j];
    }
}

// ---------------------------------------------------------------------------
// kernel_launch
// ---------------------------------------------------------------------------
extern "C" void kernel_launch(void* const* d_in, const int* in_sizes, int n_in,
                              void* d_out, int out_size) {
    const float* input_seq  = (const float*)d_in[0];
    const void*  lens_raw   = d_in[1];
    const float* output_seq = (const float*)d_in[2];
    const float* Wk         = (const float*)d_in[3];
    const float* Wv         = (const float*)d_in[4];
    const float* Wq         = (const float*)d_in[5];

    const long long CTX = (long long)Bn * Ln * Dn;   // 16,777,216
    const long long ATT = (long long)Bn * Ln * Ln;   // 33,554,432

    float *qp, *kp, *vp, *ctx_s, *attn_s;
    cudaGetSymbolAddress((void**)&qp,     g_q);
    cudaGetSymbolAddress((void**)&kp,     g_k);
    cudaGetSymbolAddress((void**)&vp,     g_v);
    cudaGetSymbolAddress((void**)&ctx_s,  g_ctx_scratch);
    cudaGetSymbolAddress((void**)&attn_s, g_attn_scratch);

    float* ctx;
    float* attn;
    if ((long long)out_size >= CTX + ATT) {        // (context, attn) concatenated
        ctx  = (float*)d_out;
        attn = (float*)d_out + CTX;
    } else if ((long long)out_size == ATT) {       // attn only
        attn = (float*)d_out;
        ctx  = ctx_s;
    } else {                                       // context only
        ctx  = (float*)d_out;
        attn = attn_s;
    }

    prep_lens_kernel<<<1, 32>>>(lens_raw);

    dim3 thr(256);
    // Projections: y = x @ W^T  (NT)
    gemm_nt_kernel<<<dim3(Dn / 64, M_ALL / 64), thr>>>(input_seq,  Wk, kp, M_ALL, Dn, Dn);
    gemm_nt_kernel<<<dim3(Dn / 64, M_ALL / 64), thr>>>(input_seq,  Wv, vp, M_ALL, Dn, Dn);
    gemm_nt_kernel<<<dim3(Dn / 64, M_ALL / 64), thr>>>(output_seq, Wq, qp, M_ALL, Dn, Dn);

    // Scores (+ scale + query-row mask) -> attn buffer (raw, pre-softmax)
    scores_kernel<<<dim3(Ln / 64, Ln / 64, Bn), thr>>>(attn);

    // Row softmax in place
    softmax_kernel<<<Bn * Ln, 256>>>(attn);

    // Context = attn @ V
    ctx_kernel<<<dim3(Dn / 64, Ln / 64, Bn), thr>>>(attn, ctx);
}

// round 3
// speedup vs baseline: 2.4576x; 2.4576x over previous
#include <cuda_runtime.h>
#include <cuda_bf16.h>
#include <math.h>
#include <stdint.h>

#define Bn 8
#define Ln 2048
#define Dn 1024
#define M_ALL (Bn * Ln)   // 16384

// ---------------------------------------------------------------------------
// Device scratch (allocation-free rule -> __device__ globals)
// ---------------------------------------------------------------------------
__device__ float g_qf[(size_t)M_ALL * Dn];
__device__ float g_kf[(size_t)M_ALL * Dn];
__device__ float g_vf[(size_t)M_ALL * Dn];
__device__ float g_ctx_scratch[(size_t)M_ALL * Dn];
__device__ float g_attn_scratch[(size_t)Bn * Ln * Ln];
__device__ int   g_lens[Bn];

// bf16 hi/lo expanded operands (K' = 3K)
__device__ __nv_bfloat16 g_Xa[(size_t)M_ALL * 3 * Dn];
__device__ __nv_bfloat16 g_Oa[(size_t)M_ALL * 3 * Dn];
__device__ __nv_bfloat16 g_Wqb[(size_t)Dn * 3 * Dn];
__device__ __nv_bfloat16 g_Wkb[(size_t)Dn * 3 * Dn];
__device__ __nv_bfloat16 g_Wvb[(size_t)Dn * 3 * Dn];
__device__ __nv_bfloat16 g_Qa[(size_t)M_ALL * 3 * Dn];
__device__ __nv_bfloat16 g_Kb[(size_t)M_ALL * 3 * Dn];
__device__ __nv_bfloat16 g_Vtb[(size_t)Bn * Dn * 3 * Ln];
__device__ __nv_bfloat16 g_Pa[(size_t)M_ALL * 3 * Ln];

// ---------------------------------------------------------------------------
// lens dtype sniffing (int64 vs int32)
// ---------------------------------------------------------------------------
__global__ void prep_lens_kernel(const void* lensraw) {
    if (threadIdx.x == 0 && blockIdx.x == 0) {
        const int* a32 = (const int*)lensraw;
        bool is64 = true;
        #pragma unroll
        for (int i = 0; i < 4; i++) {
            int lo = a32[2 * i], hi = a32[2 * i + 1];
            if (hi != 0 || lo < 1 || lo > Ln) { is64 = false; break; }
        }
        if (is64) {
            const long long* a64 = (const long long*)lensraw;
            for (int i = 0; i < Bn; i++) g_lens[i] = (int)a64[i];
        } else {
            for (int i = 0; i < Bn; i++) g_lens[i] = a32[i];
        }
    }
}

// ---------------------------------------------------------------------------
// hi/lo expansion: src fp32 [R,K] -> dst bf16 [R,3K]
//   A-pattern (isB=0): [hi | lo | hi]   B-pattern (isB=1): [hi | hi | lo]
// ---------------------------------------------------------------------------
__global__ __launch_bounds__(256)
void expand_kernel(const float* __restrict__ src, __nv_bfloat16* __restrict__ dst,
                   int K, int isB, long long total4) {
    long long i = (long long)blockIdx.x * blockDim.x + threadIdx.x;
    if (i >= total4) return;
    int K4 = K >> 2;
    long long row = i / K4;
    int kc = (int)(i - row * K4) << 2;

    float4 v = *(const float4*)(src + row * (long long)K + kc);
    float vv[4] = {v.x, v.y, v.z, v.w};
    unsigned short hb[4], lb[4];
    #pragma unroll
    for (int j = 0; j < 4; j++) {
        __nv_bfloat16 hbf = __float2bfloat16(vv[j]);
        float hf = __bfloat162float(hbf);
        __nv_bfloat16 lbf = __float2bfloat16(vv[j] - hf);
        hb[j] = __bfloat16_as_ushort(hbf);
        lb[j] = __bfloat16_as_ushort(lbf);
    }
    ushort4 hu = make_ushort4(hb[0], hb[1], hb[2], hb[3]);
    ushort4 lu = make_ushort4(lb[0], lb[1], lb[2], lb[3]);

    __nv_bfloat16* d0 = dst + row * (3LL * K) + kc;
    *(ushort4*)(d0)         = hu;
    *(ushort4*)(d0 + K)     = isB ? hu : lu;
    *(ushort4*)(d0 + 2 * K) = isB ? lu : hu;
}

// ---------------------------------------------------------------------------
// V transpose + B-pattern expand
// ---------------------------------------------------------------------------
__global__ __launch_bounds__(256)
void vtrans_kernel(const float* __restrict__ V, __nv_bfloat16* __restrict__ out) {
    __shared__ float tile[32][33];
    int d0   = blockIdx.x * 32;
    int tok0 = blockIdx.y * 32;
    int tx = threadIdx.x & 31;
    int ty = threadIdx.x >> 5;

    #pragma unroll
    for (int j = 0; j < 4; j++) {
        int y = ty + j * 8;
        tile[y][tx] = V[(size_t)(tok0 + y) * Dn + d0 + tx];
    }
    __syncthreads();

    int b = tok0 >> 11;
    int t = (tok0 & (Ln - 1)) + tx;
    #pragma unroll
    for (int j = 0; j < 4; j++) {
        int dd = d0 + ty + j * 8;
        float v = tile[tx][ty + j * 8];
        __nv_bfloat16 h = __float2bfloat16(v);
        float hf = __bfloat162float(h);
        __nv_bfloat16 l = __float2bfloat16(v - hf);
        size_t base = ((size_t)b * Dn + dd) * (3 * Ln);
        out[base + t]          = h;
        out[base + Ln + t]     = h;
        out[base + 2 * Ln + t] = l;
    }
}

// ---------------------------------------------------------------------------
// HMMA GEMM (mma.sync.m16n8k16 bf16, fp32 accum)
// C[M,N] = A'[M,K'] * B'[N,K']^T   (both K-contiguous)
// BM=BN=128, BK=64 (128B rows, SW128 swizzle), double-buffered cp.async.
// 8 warps as 2x4; warp tile 64x32. mode 1: scale + query-row mask epilogue.
// ---------------------------------------------------------------------------
__device__ __forceinline__ uint32_t sw128(uint32_t x) { return x ^ ((x >> 3) & 0x70); }

#define STAGE_B 32768
#define SMEM_REQ (1024 + 2 * STAGE_B)

__device__ __forceinline__ void cp16(uint32_t saddr, const void* gaddr) {
    asm volatile("cp.async.cg.shared.global [%0], [%1], 16;" :: "r"(saddr), "l"(gaddr));
}
__device__ __forceinline__ void cp_commit() {
    asm volatile("cp.async.commit_group;" ::: "memory");
}
template <int N> __device__ __forceinline__ void cp_wait() {
    asm volatile("cp.async.wait_group %0;" :: "n"(N) : "memory");
}
__device__ __forceinline__ void ldm4(uint32_t addr, uint32_t& r0, uint32_t& r1,
                                     uint32_t& r2, uint32_t& r3) {
    asm volatile("ldmatrix.sync.aligned.m8n8.x4.shared.b16 {%0,%1,%2,%3}, [%4];"
                 : "=r"(r0), "=r"(r1), "=r"(r2), "=r"(r3) : "r"(addr));
}
__device__ __forceinline__ void mma16816(float* c, uint32_t a0, uint32_t a1,
                                         uint32_t a2, uint32_t a3,
                                         uint32_t b0, uint32_t b1) {
    asm volatile(
        "mma.sync.aligned.m16n8k16.row.col.f32.bf16.bf16.f32 "
        "{%0,%1,%2,%3},{%4,%5,%6,%7},{%8,%9},{%0,%1,%2,%3};"
        : "+f"(c[0]), "+f"(c[1]), "+f"(c[2]), "+f"(c[3])
        : "r"(a0), "r"(a1), "r"(a2), "r"(a3), "r"(b0), "r"(b1));
}

__global__ __launch_bounds__(256, 2)
void hmma_gemm(const __nv_bfloat16* __restrict__ A, const __nv_bfloat16* __restrict__ Bm,
               float* __restrict__ C, int K, int ldc,
               long long sA, long long sB, long long sC,
               int mode, float scale) {
    extern __shared__ char dsm[];
    uint32_t sraw = (uint32_t)__cvta_generic_to_shared(dsm);
    uint32_t sb   = (sraw + 1023) & ~1023u;

    const int tid  = threadIdx.x;
    const int lane = tid & 31;
    const int wid  = tid >> 5;
    const int wr   = wid >> 2;     // 0..1
    const int wc   = wid & 3;      // 0..3
    const int z    = blockIdx.z;
    const int row0 = blockIdx.y * 128;
    const int n0   = blockIdx.x * 128;

    // ---- loader assignment: thread -> (row r, 64B half h), 4x16B per operand
    const int r = tid >> 1;
    const int h = (tid & 1) * 64;
    const size_t rs = (size_t)K * 2;
    const char* ag = (const char*)(A + (size_t)z * sA + (size_t)(row0 + r) * K) + h;
    const char* bg = (const char*)(Bm + (size_t)z * sB + (size_t)(n0 + r) * K) + h;

    uint32_t swo[4];
    #pragma unroll
    for (int i = 0; i < 4; i++) swo[i] = sw128((uint32_t)r * 128u + h + i * 16);

    float acc[4][4][4];
    #pragma unroll
    for (int a = 0; a < 4; a++)
        #pragma unroll
        for (int b = 0; b < 4; b++)
            #pragma unroll
            for (int cc = 0; cc < 4; cc++) acc[a][b][cc] = 0.0f;

    const int nch = K / 64;

    // prologue: stage 0
    {
        uint32_t sa = sb, sbB = sb + 16384;
        #pragma unroll
        for (int i = 0; i < 4; i++) {
            cp16(sa + swo[i], ag + i * 16);
            cp16(sbB + swo[i], bg + i * 16);
        }
        cp_commit();
    }

    for (int ch = 0; ch < nch; ch++) {
        if (ch + 1 < nch) {
            const int s = (ch + 1) & 1;
            uint32_t sa = sb + s * STAGE_B, sbB = sa + 16384;
            const char* agc = ag + (size_t)(ch + 1) * 128;
            const char* bgc = bg + (size_t)(ch + 1) * 128;
            #pragma unroll
            for (int i = 0; i < 4; i++) {
                cp16(sa + swo[i], agc + i * 16);
                cp16(sbB + swo[i], bgc + i * 16);
            }
            cp_commit();
            cp_wait<1>();
        } else {
            cp_wait<0>();
        }
        __syncthreads();

        const int s = ch & 1;
        const uint32_t aBase = sb + s * STAGE_B;
        const uint32_t bBase = aBase + 16384;

        #pragma unroll
        for (int kk = 0; kk < 4; kk++) {
            uint32_t af[4][4];
            #pragma unroll
            for (int mi = 0; mi < 4; mi++) {
                uint32_t row  = wr * 64 + mi * 16 + (lane & 15);
                uint32_t colb = kk * 32 + ((lane >> 4) << 4);
                uint32_t addr = aBase + sw128(row * 128u + colb);
                ldm4(addr, af[mi][0], af[mi][1], af[mi][2], af[mi][3]);
            }
            uint32_t bf[2][4];
            #pragma unroll
            for (int ni = 0; ni < 2; ni++) {
                uint32_t q    = lane >> 3;
                uint32_t row  = wc * 32 + ni * 16 + ((q >> 1) << 3) + (lane & 7);
                uint32_t colb = kk * 32 + ((q & 1) << 4);
                uint32_t addr = bBase + sw128(row * 128u + colb);
                ldm4(addr, bf[ni][0], bf[ni][1], bf[ni][2], bf[ni][3]);
            }
            #pragma unroll
            for (int mi = 0; mi < 4; mi++)
                #pragma unroll
                for (int n8 = 0; n8 < 4; n8++) {
                    uint32_t b0 = bf[n8 >> 1][(n8 & 1) * 2 + 0];
                    uint32_t b1 = bf[n8 >> 1][(n8 & 1) * 2 + 1];
                    mma16816(acc[mi][n8], af[mi][0], af[mi][1], af[mi][2], af[mi][3], b0, b1);
                }
        }
        __syncthreads();
    }

    // ---- epilogue
    const int g = lane >> 2;          // 0..7
    const int tg = lane & 3;          // 0..3
    float* Cz = C + (size_t)z * sC;
    const int len = (mode == 1) ? g_lens[z] : 0;

    #pragma unroll
    for (int mi = 0; mi < 4; mi++) {
        const int rA = row0 + wr * 64 + mi * 16 + g;
        const int rB = rA + 8;
        #pragma unroll
        for (int n8 = 0; n8 < 4; n8++) {
            const int col = n0 + wc * 32 + n8 * 8 + tg * 2;
            float v0 = acc[mi][n8][0], v1 = acc[mi][n8][1];
            float v2 = acc[mi][n8][2], v3 = acc[mi][n8][3];
            if (mode == 1) {
                bool okA = rA < len, okB = rB < len;
                v0 = okA ? v0 * scale : -1e9f;
                v1 = okA ? v1 * scale : -1e9f;
                v2 = okB ? v2 * scale : -1e9f;
                v3 = okB ? v3 * scale : -1e9f;
            }
            *(float2*)(Cz + (size_t)rA * ldc + col) = make_float2(v0, v1);
            *(float2*)(Cz + (size_t)rB * ldc + col) = make_float2(v2, v3);
        }
    }
}

// ---------------------------------------------------------------------------
// Row softmax over Ln=2048, in place.
// ---------------------------------------------------------------------------
__global__ __launch_bounds__(256)
void softmax_kernel(float* __restrict__ attn) {
    const size_t row = blockIdx.x;
    float* p = attn + row * Ln;
    const int t = threadIdx.x;

    float v[8];
    float m = -INFINITY;
    #pragma unroll
    for (int i = 0; i < 8; i++) {
        v[i] = p[t + i * 256];
        m = fmaxf(m, v[i]);
    }

    __shared__ float red[256];
    red[t] = m;
    __syncthreads();
    #pragma unroll
    for (int s = 128; s > 0; s >>= 1) {
        if (t < s) red[t] = fmaxf(red[t], red[t + s]);
        __syncthreads();
    }
    m = red[0];
    __syncthreads();

    float sum = 0.0f;
    #pragma unroll
    for (int i = 0; i < 8; i++) {
        v[i] = expf(v[i] - m);
        sum += v[i];
    }
    red[t] = sum;
    __syncthreads();
    #pragma unroll
    for (int s = 128; s > 0; s >>= 1) {
        if (t < s) red[t] += red[t + s];
        __syncthreads();
    }
    const float inv = 1.0f / red[0];

    #pragma unroll
    for (int i = 0; i < 8; i++)
        p[t + i * 256] = v[i] * inv;
}

// ---------------------------------------------------------------------------
// kernel_launch
// ---------------------------------------------------------------------------
extern "C" void kernel_launch(void* const* d_in, const int* in_sizes, int n_in,
                              void* d_out, int out_size) {
    const float* X  = (const float*)d_in[0];
    const void*  lens_raw = d_in[1];
    const float* O  = (const float*)d_in[2];
    const float* Wk = (const float*)d_in[3];
    const float* Wv = (const float*)d_in[4];
    const float* Wq = (const float*)d_in[5];

    const long long CTX = (long long)Bn * Ln * Dn;
    const long long ATT = (long long)Bn * Ln * Ln;

    float *qf, *kf, *vf, *ctx_s, *attn_s;
    __nv_bfloat16 *Xa, *Oa, *Wqb, *Wkb, *Wvb, *Qa, *Kb, *Vtb, *Pa;
    cudaGetSymbolAddress((void**)&qf, g_qf);
    cudaGetSymbolAddress((void**)&kf, g_kf);
    cudaGetSymbolAddress((void**)&vf, g_vf);
    cudaGetSymbolAddress((void**)&ctx_s, g_ctx_scratch);
    cudaGetSymbolAddress((void**)&attn_s, g_attn_scratch);
    cudaGetSymbolAddress((void**)&Xa, g_Xa);
    cudaGetSymbolAddress((void**)&Oa, g_Oa);
    cudaGetSymbolAddress((void**)&Wqb, g_Wqb);
    cudaGetSymbolAddress((void**)&Wkb, g_Wkb);
    cudaGetSymbolAddress((void**)&Wvb, g_Wvb);
    cudaGetSymbolAddress((void**)&Qa, g_Qa);
    cudaGetSymbolAddress((void**)&Kb, g_Kb);
    cudaGetSymbolAddress((void**)&Vtb, g_Vtb);
    cudaGetSymbolAddress((void**)&Pa, g_Pa);

    float* ctx;
    float* attn;
    if ((long long)out_size >= CTX + ATT) {
        ctx  = (float*)d_out;
        attn = (float*)d_out + CTX;
    } else if ((long long)out_size == ATT) {
        attn = (float*)d_out;
        ctx  = ctx_s;
    } else {
        ctx  = (float*)d_out;
        attn = attn_s;
    }

    cudaFuncSetAttribute(hmma_gemm, cudaFuncAttributeMaxDynamicSharedMemorySize, SMEM_REQ);

    prep_lens_kernel<<<1, 32>>>(lens_raw);

    // hi/lo expansions of raw inputs
    {
        long long t4 = (long long)M_ALL * Dn / 4;
        int blocks = (int)((t4 + 255) / 256);
        expand_kernel<<<blocks, 256>>>(X, Xa, Dn, 0, t4);
        expand_kernel<<<blocks, 256>>>(O, Oa, Dn, 0, t4);
        long long w4 = (long long)Dn * Dn / 4;
        int wb = (int)((w4 + 255) / 256);
        expand_kernel<<<wb, 256>>>(Wq, Wqb, Dn, 1, w4);
        expand_kernel<<<wb, 256>>>(Wk, Wkb, Dn, 1, w4);
        expand_kernel<<<wb, 256>>>(Wv, Wvb, Dn, 1, w4);
    }

    // Projections (fp32 out): M=16384, N=1024, K'=3072
    {
        dim3 grid(Dn / 128, M_ALL / 128, 1);
        hmma_gemm<<<grid, 256, SMEM_REQ>>>(Oa, Wqb, qf, 3 * Dn, Dn, 0, 0, 0, 0, 1.0f);
        hmma_gemm<<<grid, 256, SMEM_REQ>>>(Xa, Wkb, kf, 3 * Dn, Dn, 0, 0, 0, 0, 1.0f);
        hmma_gemm<<<grid, 256, SMEM_REQ>>>(Xa, Wvb, vf, 3 * Dn, Dn, 0, 0, 0, 0, 1.0f);
    }

    // Expand q (A-pattern), k (B-pattern); transpose+expand v
    {
        long long t4 = (long long)M_ALL * Dn / 4;
        int blocks = (int)((t4 + 255) / 256);
        expand_kernel<<<blocks, 256>>>(qf, Qa, Dn, 0, t4);
        expand_kernel<<<blocks, 256>>>(kf, Kb, Dn, 1, t4);
        vtrans_kernel<<<dim3(Dn / 32, M_ALL / 32), 256>>>(vf, Vtb);
    }

    // Scores: per batch M=2048, N=2048, K'=3072; scale+mask epilogue
    {
        dim3 grid(Ln / 128, Ln / 128, Bn);
        hmma_gemm<<<grid, 256, SMEM_REQ>>>(Qa, Kb, attn, 3 * Dn, Ln,
                                           (long long)Ln * 3 * Dn, (long long)Ln * 3 * Dn,
                                           (long long)Ln * Ln, 1, 0.03125f);
    }

    // Softmax in place
    softmax_kernel<<<Bn * Ln, 256>>>(attn);

    // Expand attn (A-pattern): [16384, 2048] -> [16384, 6144]
    {
        long long t4 = (long long)M_ALL * Ln / 4;
        int blocks = (int)((t4 + 255) / 256);
        expand_kernel<<<blocks, 256>>>(attn, Pa, Ln, 0, t4);
    }

    // Context: per batch M=2048, N=1024, K'=6144
    {
        dim3 grid(Dn / 128, Ln / 128, Bn);
        hmma_gemm<<<grid, 256, SMEM_REQ>>>(Pa, Vtb, ctx, 3 * Ln, Dn,
                                           (long long)Ln * 3 * Ln, (long long)Dn * 3 * Ln,
                                           (long long)Ln * Dn, 0, 1.0f);
    }
}

// round 4
// speedup vs baseline: 2.5547x; 1.0395x over previous
#include <cuda_runtime.h>
#include <cuda_bf16.h>
#include <math.h>
#include <stdint.h>

#define Bn 8
#define Ln 2048
#define Dn 1024
#define M_ALL (Bn * Ln)   // 16384

// ---------------------------------------------------------------------------
// Device scratch (allocation-free rule -> __device__ globals)
// ---------------------------------------------------------------------------
__device__ float g_vf[(size_t)M_ALL * Dn];
__device__ float g_ctx_scratch[(size_t)M_ALL * Dn];
__device__ float g_attn_scratch[(size_t)Bn * Ln * Ln];
__device__ int   g_lens[Bn];

// hi/lo bf16 planes
__device__ __nv_bfloat16 g_Xh[(size_t)M_ALL * Dn];
__device__ __nv_bfloat16 g_Xl[(size_t)M_ALL * Dn];
__device__ __nv_bfloat16 g_Oh[(size_t)M_ALL * Dn];
__device__ __nv_bfloat16 g_Ol[(size_t)M_ALL * Dn];
__device__ __nv_bfloat16 g_Wqh[(size_t)Dn * Dn];
__device__ __nv_bfloat16 g_Wql[(size_t)Dn * Dn];
__device__ __nv_bfloat16 g_Wkh[(size_t)Dn * Dn];
__device__ __nv_bfloat16 g_Wkl[(size_t)Dn * Dn];
__device__ __nv_bfloat16 g_Wvh[(size_t)Dn * Dn];
__device__ __nv_bfloat16 g_Wvl[(size_t)Dn * Dn];
__device__ __nv_bfloat16 g_Qh[(size_t)M_ALL * Dn];
__device__ __nv_bfloat16 g_Ql[(size_t)M_ALL * Dn];
__device__ __nv_bfloat16 g_Kh[(size_t)M_ALL * Dn];
__device__ __nv_bfloat16 g_Kl[(size_t)M_ALL * Dn];
__device__ __nv_bfloat16 g_Vth[(size_t)Bn * Dn * Ln];
__device__ __nv_bfloat16 g_Vtl[(size_t)Bn * Dn * Ln];
__device__ __nv_bfloat16 g_Ph[(size_t)M_ALL * Ln];
__device__ __nv_bfloat16 g_Pl[(size_t)M_ALL * Ln];

// ---------------------------------------------------------------------------
// lens dtype sniffing (int64 vs int32)
// ---------------------------------------------------------------------------
__global__ void prep_lens_kernel(const void* lensraw) {
    if (threadIdx.x == 0 && blockIdx.x == 0) {
        const int* a32 = (const int*)lensraw;
        bool is64 = true;
        #pragma unroll
        for (int i = 0; i < 4; i++) {
            int lo = a32[2 * i], hi = a32[2 * i + 1];
            if (hi != 0 || lo < 1 || lo > Ln) { is64 = false; break; }
        }
        if (is64) {
            const long long* a64 = (const long long*)lensraw;
            for (int i = 0; i < Bn; i++) g_lens[i] = (int)a64[i];
        } else {
            for (int i = 0; i < Bn; i++) g_lens[i] = a32[i];
        }
    }
}

// ---------------------------------------------------------------------------
// fp32 -> (hi, lo) bf16 planes, flat
// ---------------------------------------------------------------------------
__global__ __launch_bounds__(256)
void expand2_kernel(const float* __restrict__ src, __nv_bfloat16* __restrict__ dh,
                    __nv_bfloat16* __restrict__ dl, long long total4) {
    long long i = (long long)blockIdx.x * blockDim.x + threadIdx.x;
    if (i >= total4) return;
    float4 v = *(const float4*)(src + i * 4);
    float vv[4] = {v.x, v.y, v.z, v.w};
    unsigned short hb[4], lb[4];
    #pragma unroll
    for (int j = 0; j < 4; j++) {
        __nv_bfloat16 hbf = __float2bfloat16(vv[j]);
        float hf = __bfloat162float(hbf);
        __nv_bfloat16 lbf = __float2bfloat16(vv[j] - hf);
        hb[j] = __bfloat16_as_ushort(hbf);
        lb[j] = __bfloat16_as_ushort(lbf);
    }
    *(ushort4*)(dh + i * 4) = make_ushort4(hb[0], hb[1], hb[2], hb[3]);
    *(ushort4*)(dl + i * 4) = make_ushort4(lb[0], lb[1], lb[2], lb[3]);
}

// ---------------------------------------------------------------------------
// V transpose + hi/lo split: vf [16384 tok, 1024 d] -> per batch [1024 d, 2048 tok]
// ---------------------------------------------------------------------------
__global__ __launch_bounds__(256)
void vtrans_kernel(const float* __restrict__ V, __nv_bfloat16* __restrict__ oh,
                   __nv_bfloat16* __restrict__ ol) {
    __shared__ float tile[32][33];
    int d0   = blockIdx.x * 32;
    int tok0 = blockIdx.y * 32;
    int tx = threadIdx.x & 31;
    int ty = threadIdx.x >> 5;

    #pragma unroll
    for (int j = 0; j < 4; j++) {
        int y = ty + j * 8;
        tile[y][tx] = V[(size_t)(tok0 + y) * Dn + d0 + tx];
    }
    __syncthreads();

    int b = tok0 >> 11;
    int t = (tok0 & (Ln - 1)) + tx;
    #pragma unroll
    for (int j = 0; j < 4; j++) {
        int dd = d0 + ty + j * 8;
        float v = tile[tx][ty + j * 8];
        __nv_bfloat16 h = __float2bfloat16(v);
        float hf = __bfloat162float(h);
        __nv_bfloat16 l = __float2bfloat16(v - hf);
        size_t base = ((size_t)b * Dn + dd) * Ln + t;
        oh[base] = h;
        ol[base] = l;
    }
}

// ---------------------------------------------------------------------------
// HMMA GEMM core (mma.sync m16n8k16 bf16, fp32 accum), NT.
// 3 K-segments over hi/lo planes: (Ah,Bh), (Ah,Bl), (Al,Bh).
// BM=BN=128, BK=64, 3-stage cp.async, 8 warps 2x4, warp tile 64x32.
// MODE 0: fp32 C. MODE 1: scale+mask fp32 C. MODE 2: write hi/lo bf16 planes.
// ---------------------------------------------------------------------------
__device__ __forceinline__ uint32_t sw128(uint32_t x) { return x ^ ((x >> 3) & 0x70); }

#define STAGE_B 32768
#define NSTAGE  3
#define SMEM_REQ (1024 + NSTAGE * STAGE_B)

__device__ __forceinline__ void cp16(uint32_t saddr, const void* gaddr) {
    asm volatile("cp.async.cg.shared.global [%0], [%1], 16;" :: "r"(saddr), "l"(gaddr));
}
__device__ __forceinline__ void cp_commit() {
    asm volatile("cp.async.commit_group;" ::: "memory");
}
template <int N> __device__ __forceinline__ void cp_wait() {
    asm volatile("cp.async.wait_group %0;" :: "n"(N) : "memory");
}
__device__ __forceinline__ void ldm4(uint32_t addr, uint32_t& r0, uint32_t& r1,
                                     uint32_t& r2, uint32_t& r3) {
    asm volatile("ldmatrix.sync.aligned.m8n8.x4.shared.b16 {%0,%1,%2,%3}, [%4];"
                 : "=r"(r0), "=r"(r1), "=r"(r2), "=r"(r3) : "r"(addr));
}
__device__ __forceinline__ void mma16816(float* c, uint32_t a0, uint32_t a1,
                                         uint32_t a2, uint32_t a3,
                                         uint32_t b0, uint32_t b1) {
    asm volatile(
        "mma.sync.aligned.m16n8k16.row.col.f32.bf16.bf16.f32 "
        "{%0,%1,%2,%3},{%4,%5,%6,%7},{%8,%9},{%0,%1,%2,%3};"
        : "+f"(c[0]), "+f"(c[1]), "+f"(c[2]), "+f"(c[3])
        : "r"(a0), "r"(a1), "r"(a2), "r"(a3), "r"(b0), "r"(b1));
}
__device__ __forceinline__ uint32_t pack_bf2(__nv_bfloat16 a, __nv_bfloat16 b) {
    return (uint32_t)__bfloat16_as_ushort(a) | ((uint32_t)__bfloat16_as_ushort(b) << 16);
}

template <int MODE>
__global__ __launch_bounds__(256, 2)
void hmma_gemm(const __nv_bfloat16* __restrict__ Ah, const __nv_bfloat16* __restrict__ Al,
               const __nv_bfloat16* __restrict__ Bh, const __nv_bfloat16* __restrict__ Bl,
               float* __restrict__ C,
               __nv_bfloat16* __restrict__ Poh, __nv_bfloat16* __restrict__ Pol,
               int K, int ldc,
               long long sA, long long sB, long long sC, float scale) {
    extern __shared__ char dsm[];
    uint32_t sraw = (uint32_t)__cvta_generic_to_shared(dsm);
    uint32_t sb   = (sraw + 1023) & ~1023u;

    const int tid  = threadIdx.x;
    const int lane = tid & 31;
    const int wid  = tid >> 5;
    const int wr   = wid >> 2;
    const int wc   = wid & 3;
    const int z    = blockIdx.z;
    const int row0 = blockIdx.y * 128;
    const int n0   = blockIdx.x * 128;

    // loader: thread -> (row r, 64B half h)
    const int r = tid >> 1;
    const int h = (tid & 1) * 64;

    const char* aRowH = (const char*)(Ah + (size_t)z * sA + (size_t)(row0 + r) * K) + h;
    const char* aRowL = (const char*)(Al + (size_t)z * sA + (size_t)(row0 + r) * K) + h;
    const char* bRowH = (const char*)(Bh + (size_t)z * sB + (size_t)(n0 + r) * K) + h;
    const char* bRowL = (const char*)(Bl + (size_t)z * sB + (size_t)(n0 + r) * K) + h;

    uint32_t swo[4];
    #pragma unroll
    for (int i = 0; i < 4; i++) swo[i] = sw128((uint32_t)r * 128u + h + i * 16);

    float acc[4][4][4];
    #pragma unroll
    for (int a = 0; a < 4; a++)
        #pragma unroll
        for (int b = 0; b < 4; b++)
            #pragma unroll
            for (int cc = 0; cc < 4; cc++) acc[a][b][cc] = 0.0f;

    const int nch = K / 64;
    const int T   = 3 * nch;

    // issue-side cursor
    const char* aPtr = aRowH;
    const char* bPtr = bRowH;
    int cIss = 0, segIss = 0, bufIss = 0;

    auto issue_one = [&]() {
        uint32_t sa = sb + bufIss * STAGE_B;
        #pragma unroll
        for (int i = 0; i < 4; i++) {
            cp16(sa + swo[i], aPtr + i * 16);
            cp16(sa + 16384 + swo[i], bPtr + i * 16);
        }
        cp_commit();
        aPtr += 128; bPtr += 128;
        bufIss = (bufIss == NSTAGE - 1) ? 0 : bufIss + 1;
        if (++cIss == nch) {
            cIss = 0; segIss++;
            if (segIss == 1)      { aPtr = aRowH; bPtr = bRowL; }
            else if (segIss == 2) { aPtr = aRowL; bPtr = bRowH; }
        }
    };

    issue_one();
    issue_one();

    int bufC = 0;
    for (int t = 0; t < T; t++) {
        if (t + 2 < T)      { issue_one(); cp_wait<2>(); }
        else if (t + 1 < T) { cp_wait<1>(); }
        else                { cp_wait<0>(); }
        __syncthreads();

        const uint32_t aBase = sb + bufC * STAGE_B;
        const uint32_t bBase = aBase + 16384;

        #pragma unroll
        for (int kk = 0; kk < 4; kk++) {
            uint32_t af[4][4];
            #pragma unroll
            for (int mi = 0; mi < 4; mi++) {
                uint32_t row  = wr * 64 + mi * 16 + (lane & 15);
                uint32_t colb = kk * 32 + ((lane >> 4) << 4);
                ldm4(aBase + sw128(row * 128u + colb), af[mi][0], af[mi][1], af[mi][2], af[mi][3]);
            }
            uint32_t bf[2][4];
            #pragma unroll
            for (int ni = 0; ni < 2; ni++) {
                uint32_t q    = lane >> 3;
                uint32_t row  = wc * 32 + ni * 16 + ((q >> 1) << 3) + (lane & 7);
                uint32_t colb = kk * 32 + ((q & 1) << 4);
                ldm4(bBase + sw128(row * 128u + colb), bf[ni][0], bf[ni][1], bf[ni][2], bf[ni][3]);
            }
            #pragma unroll
            for (int mi = 0; mi < 4; mi++)
                #pragma unroll
                for (int n8 = 0; n8 < 4; n8++) {
                    uint32_t b0 = bf[n8 >> 1][(n8 & 1) * 2 + 0];
                    uint32_t b1 = bf[n8 >> 1][(n8 & 1) * 2 + 1];
                    mma16816(acc[mi][n8], af[mi][0], af[mi][1], af[mi][2], af[mi][3], b0, b1);
                }
        }
        __syncthreads();
        bufC = (bufC == NSTAGE - 1) ? 0 : bufC + 1;
    }

    // ---- epilogue
    const int g  = lane >> 2;
    const int tg = lane & 3;
    const int len = (MODE == 1) ? g_lens[z] : 0;

    #pragma unroll
    for (int mi = 0; mi < 4; mi++) {
        const int rA = row0 + wr * 64 + mi * 16 + g;
        const int rB = rA + 8;
        #pragma unroll
        for (int n8 = 0; n8 < 4; n8++) {
            const int col = n0 + wc * 32 + n8 * 8 + tg * 2;
            float v0 = acc[mi][n8][0], v1 = acc[mi][n8][1];
            float v2 = acc[mi][n8][2], v3 = acc[mi][n8][3];
            if (MODE == 0) {
                float* Cz = C + (size_t)z * sC;
                *(float2*)(Cz + (size_t)rA * ldc + col) = make_float2(v0, v1);
                *(float2*)(Cz + (size_t)rB * ldc + col) = make_float2(v2, v3);
            } else if (MODE == 1) {
                float* Cz = C + (size_t)z * sC;
                bool okA = rA < len, okB = rB < len;
                *(float2*)(Cz + (size_t)rA * ldc + col) =
                    make_float2(okA ? v0 * scale : -1e9f, okA ? v1 * scale : -1e9f);
                *(float2*)(Cz + (size_t)rB * ldc + col) =
                    make_float2(okB ? v2 * scale : -1e9f, okB ? v3 * scale : -1e9f);
            } else {
                __nv_bfloat16 h0 = __float2bfloat16(v0), h1 = __float2bfloat16(v1);
                __nv_bfloat16 h2 = __float2bfloat16(v2), h3 = __float2bfloat16(v3);
                __nv_bfloat16 l0 = __float2bfloat16(v0 - __bfloat162float(h0));
                __nv_bfloat16 l1 = __float2bfloat16(v1 - __bfloat162float(h1));
                __nv_bfloat16 l2 = __float2bfloat16(v2 - __bfloat162float(h2));
                __nv_bfloat16 l3 = __float2bfloat16(v3 - __bfloat162float(h3));
                *(uint32_t*)(Poh + (size_t)rA * ldc + col) = pack_bf2(h0, h1);
                *(uint32_t*)(Poh + (size_t)rB * ldc + col) = pack_bf2(h2, h3);
                *(uint32_t*)(Pol + (size_t)rA * ldc + col) = pack_bf2(l0, l1);
                *(uint32_t*)(Pol + (size_t)rB * ldc + col) = pack_bf2(l2, l3);
            }
        }
    }
}

// ---------------------------------------------------------------------------
// Row softmax over Ln=2048, in place + hi/lo bf16 plane outputs.
// Thread t owns elems [t*8, t*8+8).
// ---------------------------------------------------------------------------
__global__ __launch_bounds__(256)
void softmax_kernel(float* __restrict__ attn, __nv_bfloat16* __restrict__ Ph,
                    __nv_bfloat16* __restrict__ Pl) {
    const size_t row = blockIdx.x;
    float* p = attn + row * Ln;
    const int t = threadIdx.x;

    float4 va = ((const float4*)p)[t * 2];
    float4 vb = ((const float4*)p)[t * 2 + 1];
    float v[8] = {va.x, va.y, va.z, va.w, vb.x, vb.y, vb.z, vb.w};

    float m = v[0];
    #pragma unroll
    for (int i = 1; i < 8; i++) m = fmaxf(m, v[i]);

    __shared__ float red[256];
    red[t] = m;
    __syncthreads();
    #pragma unroll
    for (int s = 128; s > 0; s >>= 1) {
        if (t < s) red[t] = fmaxf(red[t], red[t + s]);
        __syncthreads();
    }
    m = red[0];
    __syncthreads();

    float sum = 0.0f;
    #pragma unroll
    for (int i = 0; i < 8; i++) {
        v[i] = expf(v[i] - m);
        sum += v[i];
    }
    red[t] = sum;
    __syncthreads();
    #pragma unroll
    for (int s = 128; s > 0; s >>= 1) {
        if (t < s) red[t] += red[t + s];
        __syncthreads();
    }
    const float inv = 1.0f / red[0];

    unsigned short hb[8], lb[8];
    #pragma unroll
    for (int i = 0; i < 8; i++) {
        v[i] *= inv;
        __nv_bfloat16 hbf = __float2bfloat16(v[i]);
        float hf = __bfloat162float(hbf);
        __nv_bfloat16 lbf = __float2bfloat16(v[i] - hf);
        hb[i] = __bfloat16_as_ushort(hbf);
        lb[i] = __bfloat16_as_ushort(lbf);
    }
    ((float4*)p)[t * 2]     = make_float4(v[0], v[1], v[2], v[3]);
    ((float4*)p)[t * 2 + 1] = make_float4(v[4], v[5], v[6], v[7]);
    __nv_bfloat16* ph = Ph + row * Ln + t * 8;
    __nv_bfloat16* pl = Pl + row * Ln + t * 8;
    *(ushort4*)(ph)     = make_ushort4(hb[0], hb[1], hb[2], hb[3]);
    *(ushort4*)(ph + 4) = make_ushort4(hb[4], hb[5], hb[6], hb[7]);
    *(ushort4*)(pl)     = make_ushort4(lb[0], lb[1], lb[2], lb[3]);
    *(ushort4*)(pl + 4) = make_ushort4(lb[4], lb[5], lb[6], lb[7]);
}

// ---------------------------------------------------------------------------
// kernel_launch
// ---------------------------------------------------------------------------
extern "C" void kernel_launch(void* const* d_in, const int* in_sizes, int n_in,
                              void* d_out, int out_size) {
    const float* X  = (const float*)d_in[0];
    const void*  lens_raw = d_in[1];
    const float* O  = (const float*)d_in[2];
    const float* Wk = (const float*)d_in[3];
    const float* Wv = (const float*)d_in[4];
    const float* Wq = (const float*)d_in[5];

    const long long CTX = (long long)Bn * Ln * Dn;
    const long long ATT = (long long)Bn * Ln * Ln;

    float *vf, *ctx_s, *attn_s;
    __nv_bfloat16 *Xh, *Xl, *Oh, *Ol, *Wqh, *Wql, *Wkh, *Wkl, *Wvh, *Wvl;
    __nv_bfloat16 *Qh, *Ql, *Kh, *Kl, *Vth, *Vtl, *Ph, *Pl;
    cudaGetSymbolAddress((void**)&vf, g_vf);
    cudaGetSymbolAddress((void**)&ctx_s, g_ctx_scratch);
    cudaGetSymbolAddress((void**)&attn_s, g_attn_scratch);
    cudaGetSymbolAddress((void**)&Xh, g_Xh);  cudaGetSymbolAddress((void**)&Xl, g_Xl);
    cudaGetSymbolAddress((void**)&Oh, g_Oh);  cudaGetSymbolAddress((void**)&Ol, g_Ol);
    cudaGetSymbolAddress((void**)&Wqh, g_Wqh); cudaGetSymbolAddress((void**)&Wql, g_Wql);
    cudaGetSymbolAddress((void**)&Wkh, g_Wkh); cudaGetSymbolAddress((void**)&Wkl, g_Wkl);
    cudaGetSymbolAddress((void**)&Wvh, g_Wvh); cudaGetSymbolAddress((void**)&Wvl, g_Wvl);
    cudaGetSymbolAddress((void**)&Qh, g_Qh);  cudaGetSymbolAddress((void**)&Ql, g_Ql);
    cudaGetSymbolAddress((void**)&Kh, g_Kh);  cudaGetSymbolAddress((void**)&Kl, g_Kl);
    cudaGetSymbolAddress((void**)&Vth, g_Vth); cudaGetSymbolAddress((void**)&Vtl, g_Vtl);
    cudaGetSymbolAddress((void**)&Ph, g_Ph);  cudaGetSymbolAddress((void**)&Pl, g_Pl);

    float* ctx;
    float* attn;
    if ((long long)out_size >= CTX + ATT) {
        ctx  = (float*)d_out;
        attn = (float*)d_out + CTX;
    } else if ((long long)out_size == ATT) {
        attn = (float*)d_out;
        ctx  = ctx_s;
    } else {
        ctx  = (float*)d_out;
        attn = attn_s;
    }

    cudaFuncSetAttribute(hmma_gemm<0>, cudaFuncAttributeMaxDynamicSharedMemorySize, SMEM_REQ);
    cudaFuncSetAttribute(hmma_gemm<1>, cudaFuncAttributeMaxDynamicSharedMemorySize, SMEM_REQ);
    cudaFuncSetAttribute(hmma_gemm<2>, cudaFuncAttributeMaxDynamicSharedMemorySize, SMEM_REQ);

    prep_lens_kernel<<<1, 32>>>(lens_raw);

    // hi/lo expansions of raw inputs
    {
        long long t4 = (long long)M_ALL * Dn / 4;
        int blocks = (int)((t4 + 255) / 256);
        expand2_kernel<<<blocks, 256>>>(X, Xh, Xl, t4);
        expand2_kernel<<<blocks, 256>>>(O, Oh, Ol, t4);
        long long w4 = (long long)Dn * Dn / 4;
        int wb = (int)((w4 + 255) / 256);
        expand2_kernel<<<wb, 256>>>(Wq, Wqh, Wql, w4);
        expand2_kernel<<<wb, 256>>>(Wk, Wkh, Wkl, w4);
        expand2_kernel<<<wb, 256>>>(Wv, Wvh, Wvl, w4);
    }

    // Projections: M=16384, N=1024, K=1024
    {
        dim3 grid(Dn / 128, M_ALL / 128, 1);
        // q: bf16 hi/lo planes out
        hmma_gemm<2><<<grid, 256, SMEM_REQ>>>(Oh, Ol, Wqh, Wql, nullptr, Qh, Ql,
                                              Dn, Dn, 0, 0, 0, 1.0f);
        // k: bf16 hi/lo planes out
        hmma_gemm<2><<<grid, 256, SMEM_REQ>>>(Xh, Xl, Wkh, Wkl, nullptr, Kh, Kl,
                                              Dn, Dn, 0, 0, 0, 1.0f);
        // v: fp32 out (for transpose)
        hmma_gemm<0><<<grid, 256, SMEM_REQ>>>(Xh, Xl, Wvh, Wvl, vf, nullptr, nullptr,
                                              Dn, Dn, 0, 0, 0, 1.0f);
    }

    // V transpose + split
    vtrans_kernel<<<dim3(Dn / 32, M_ALL / 32), 256>>>(vf, Vth, Vtl);

    // Scores: per batch M=N=2048, K=1024; scale + query-row mask
    {
        dim3 grid(Ln / 128, Ln / 128, Bn);
        hmma_gemm<1><<<grid, 256, SMEM_REQ>>>(Qh, Ql, Kh, Kl, attn, nullptr, nullptr,
                                              Dn, Ln, (long long)Ln * Dn, (long long)Ln * Dn,
                                              (long long)Ln * Ln, 0.03125f);
    }

    // Softmax in place + P hi/lo planes
    softmax_kernel<<<Bn * Ln, 256>>>(attn, Ph, Pl);

    // Context: per batch M=2048, N=1024, K=2048
    {
        dim3 grid(Dn / 128, Ln / 128, Bn);
        hmma_gemm<0><<<grid, 256, SMEM_REQ>>>(Ph, Pl, Vth, Vtl, ctx, nullptr, nullptr,
                                              Ln, Dn, (long long)Ln * Ln, (long long)Dn * Ln,
                                              (long long)Ln * Dn, 1.0f);
    }
}

// round 5
// speedup vs baseline: 3.4128x; 1.3359x over previous
#include <cuda_runtime.h>
#include <cuda_bf16.h>
#include <math.h>
#include <stdint.h>

#define Bn 8
#define Ln 2048
#define Dn 1024
#define M_ALL (Bn * Ln)   // 16384

// ---------------------------------------------------------------------------
// Device scratch (allocation-free rule -> __device__ globals)
// ---------------------------------------------------------------------------
__device__ float g_vf[(size_t)M_ALL * Dn];
__device__ float g_ctx_scratch[(size_t)M_ALL * Dn];
__device__ float g_attn_scratch[(size_t)Bn * Ln * Ln];
__device__ float g_vmean[(size_t)Bn * Dn];
__device__ int   g_lens[Bn];

// hi/lo bf16 planes
__device__ __nv_bfloat16 g_Xh[(size_t)M_ALL * Dn];
__device__ __nv_bfloat16 g_Xl[(size_t)M_ALL * Dn];
__device__ __nv_bfloat16 g_Oh[(size_t)M_ALL * Dn];
__device__ __nv_bfloat16 g_Ol[(size_t)M_ALL * Dn];
__device__ __nv_bfloat16 g_Wqh[(size_t)Dn * Dn];
__device__ __nv_bfloat16 g_Wql[(size_t)Dn * Dn];
__device__ __nv_bfloat16 g_Wkh[(size_t)Dn * Dn];
__device__ __nv_bfloat16 g_Wkl[(size_t)Dn * Dn];
__device__ __nv_bfloat16 g_Wvh[(size_t)Dn * Dn];
__device__ __nv_bfloat16 g_Wvl[(size_t)Dn * Dn];
__device__ __nv_bfloat16 g_Qh[(size_t)M_ALL * Dn];
__device__ __nv_bfloat16 g_Ql[(size_t)M_ALL * Dn];
__device__ __nv_bfloat16 g_Kh[(size_t)M_ALL * Dn];
__device__ __nv_bfloat16 g_Kl[(size_t)M_ALL * Dn];
__device__ __nv_bfloat16 g_Vth[(size_t)Bn * Dn * Ln];
__device__ __nv_bfloat16 g_Vtl[(size_t)Bn * Dn * Ln];
__device__ __nv_bfloat16 g_Ph[(size_t)M_ALL * Ln];
__device__ __nv_bfloat16 g_Pl[(size_t)M_ALL * Ln];

// ---------------------------------------------------------------------------
// lens dtype sniffing (int64 vs int32)
// ---------------------------------------------------------------------------
__global__ void prep_lens_kernel(const void* lensraw) {
    if (threadIdx.x == 0 && blockIdx.x == 0) {
        const int* a32 = (const int*)lensraw;
        bool is64 = true;
        #pragma unroll
        for (int i = 0; i < 4; i++) {
            int lo = a32[2 * i], hi = a32[2 * i + 1];
            if (hi != 0 || lo < 1 || lo > Ln) { is64 = false; break; }
        }
        if (is64) {
            const long long* a64 = (const long long*)lensraw;
            for (int i = 0; i < Bn; i++) g_lens[i] = (int)a64[i];
        } else {
            for (int i = 0; i < Bn; i++) g_lens[i] = a32[i];
        }
    }
}

// ---------------------------------------------------------------------------
// fp32 -> (hi, lo) bf16 planes, flat
// ---------------------------------------------------------------------------
__global__ __launch_bounds__(256)
void expand2_kernel(const float* __restrict__ src, __nv_bfloat16* __restrict__ dh,
                    __nv_bfloat16* __restrict__ dl, long long total4) {
    long long i = (long long)blockIdx.x * blockDim.x + threadIdx.x;
    if (i >= total4) return;
    float4 v = *(const float4*)(src + i * 4);
    float vv[4] = {v.x, v.y, v.z, v.w};
    unsigned short hb[4], lb[4];
    #pragma unroll
    for (int j = 0; j < 4; j++) {
        __nv_bfloat16 hbf = __float2bfloat16(vv[j]);
        float hf = __bfloat162float(hbf);
        __nv_bfloat16 lbf = __float2bfloat16(vv[j] - hf);
        hb[j] = __bfloat16_as_ushort(hbf);
        lb[j] = __bfloat16_as_ushort(lbf);
    }
    *(ushort4*)(dh + i * 4) = make_ushort4(hb[0], hb[1], hb[2], hb[3]);
    *(ushort4*)(dl + i * 4) = make_ushort4(lb[0], lb[1], lb[2], lb[3]);
}

// ---------------------------------------------------------------------------
// V transpose + hi/lo split
// ---------------------------------------------------------------------------
__global__ __launch_bounds__(256)
void vtrans_kernel(const float* __restrict__ V, __nv_bfloat16* __restrict__ oh,
                   __nv_bfloat16* __restrict__ ol) {
    __shared__ float tile[32][33];
    int d0   = blockIdx.x * 32;
    int tok0 = blockIdx.y * 32;
    int tx = threadIdx.x & 31;
    int ty = threadIdx.x >> 5;

    #pragma unroll
    for (int j = 0; j < 4; j++) {
        int y = ty + j * 8;
        tile[y][tx] = V[(size_t)(tok0 + y) * Dn + d0 + tx];
    }
    __syncthreads();

    int b = tok0 >> 11;
    int t = (tok0 & (Ln - 1)) + tx;
    #pragma unroll
    for (int j = 0; j < 4; j++) {
        int dd = d0 + ty + j * 8;
        float v = tile[tx][ty + j * 8];
        __nv_bfloat16 h = __float2bfloat16(v);
        float hf = __bfloat162float(h);
        __nv_bfloat16 l = __float2bfloat16(v - hf);
        size_t base = ((size_t)b * Dn + dd) * Ln + t;
        oh[base] = h;
        ol[base] = l;
    }
}

// ---------------------------------------------------------------------------
// Per-batch V column mean: vmean[b][d] = (1/2048) * sum_t V[b*Ln+t][d]
// ---------------------------------------------------------------------------
__global__ __launch_bounds__(256)
void vmean_kernel(const float* __restrict__ vf, float* __restrict__ vm) {
    int b = blockIdx.y;
    int d = blockIdx.x * 256 + threadIdx.x;
    const float* p = vf + (size_t)b * Ln * Dn + d;
    float s0 = 0.f, s1 = 0.f, s2 = 0.f, s3 = 0.f;
    for (int t = 0; t < Ln; t += 4) {
        s0 += p[(size_t)(t + 0) * Dn];
        s1 += p[(size_t)(t + 1) * Dn];
        s2 += p[(size_t)(t + 2) * Dn];
        s3 += p[(size_t)(t + 3) * Dn];
    }
    vm[b * Dn + d] = (s0 + s1 + s2 + s3) * (1.0f / 2048.0f);
}

// ---------------------------------------------------------------------------
// Fill masked ctx rows with vmean
// ---------------------------------------------------------------------------
__global__ __launch_bounds__(256)
void fill_masked_kernel(const float* __restrict__ vm, float* __restrict__ ctx) {
    int b = blockIdx.z;
    int q = blockIdx.y;
    if (q < g_lens[b]) return;
    int d = blockIdx.x * 256 + threadIdx.x;
    ctx[((size_t)b * Ln + q) * Dn + d] = vm[b * Dn + d];
}

// ---------------------------------------------------------------------------
// HMMA GEMM core (mma.sync m16n8k16 bf16, fp32 accum), NT.
// 3 K-segments over hi/lo planes: (Ah,Bh), (Ah,Bl), (Al,Bh).
// BM=BN=128, BK=64, 3-stage cp.async, 8 warps 2x4, warp tile 64x32.
// MODE 0: fp32 C. MODE 1: scale+mask fp32 C. MODE 2: write hi/lo bf16 planes.
// skipMode 1: skip tile if local row0 >= lens[z]
// skipMode 2: skip tile if (row0 & 2047) >= lens[row0 >> 11]
// ---------------------------------------------------------------------------
__device__ __forceinline__ uint32_t sw128(uint32_t x) { return x ^ ((x >> 3) & 0x70); }

#define STAGE_B 32768
#define NSTAGE  3
#define SMEM_REQ (1024 + NSTAGE * STAGE_B)

__device__ __forceinline__ void cp16(uint32_t saddr, const void* gaddr) {
    asm volatile("cp.async.cg.shared.global [%0], [%1], 16;" :: "r"(saddr), "l"(gaddr));
}
__device__ __forceinline__ void cp_commit() {
    asm volatile("cp.async.commit_group;" ::: "memory");
}
template <int N> __device__ __forceinline__ void cp_wait() {
    asm volatile("cp.async.wait_group %0;" :: "n"(N) : "memory");
}
__device__ __forceinline__ void ldm4(uint32_t addr, uint32_t& r0, uint32_t& r1,
                                     uint32_t& r2, uint32_t& r3) {
    asm volatile("ldmatrix.sync.aligned.m8n8.x4.shared.b16 {%0,%1,%2,%3}, [%4];"
                 : "=r"(r0), "=r"(r1), "=r"(r2), "=r"(r3) : "r"(addr));
}
__device__ __forceinline__ void mma16816(float* c, uint32_t a0, uint32_t a1,
                                         uint32_t a2, uint32_t a3,
                                         uint32_t b0, uint32_t b1) {
    asm volatile(
        "mma.sync.aligned.m16n8k16.row.col.f32.bf16.bf16.f32 "
        "{%0,%1,%2,%3},{%4,%5,%6,%7},{%8,%9},{%0,%1,%2,%3};"
        : "+f"(c[0]), "+f"(c[1]), "+f"(c[2]), "+f"(c[3])
        : "r"(a0), "r"(a1), "r"(a2), "r"(a3), "r"(b0), "r"(b1));
}
__device__ __forceinline__ uint32_t pack_bf2(__nv_bfloat16 a, __nv_bfloat16 b) {
    return (uint32_t)__bfloat16_as_ushort(a) | ((uint32_t)__bfloat16_as_ushort(b) << 16);
}

template <int MODE>
__global__ __launch_bounds__(256, 2)
void hmma_gemm(const __nv_bfloat16* __restrict__ Ah, const __nv_bfloat16* __restrict__ Al,
               const __nv_bfloat16* __restrict__ Bh, const __nv_bfloat16* __restrict__ Bl,
               float* __restrict__ C,
               __nv_bfloat16* __restrict__ Poh, __nv_bfloat16* __restrict__ Pol,
               int K, int ldc,
               long long sA, long long sB, long long sC, float scale, int skipMode) {
    const int z    = blockIdx.z;
    const int row0 = blockIdx.y * 128;
    const int n0   = blockIdx.x * 128;

    // length-aware tile skipping (masked query rows)
    if (skipMode == 1) {
        if (row0 >= g_lens[z]) return;
    } else if (skipMode == 2) {
        if ((row0 & (Ln - 1)) >= g_lens[row0 >> 11]) return;
    }

    extern __shared__ char dsm[];
    uint32_t sraw = (uint32_t)__cvta_generic_to_shared(dsm);
    uint32_t sb   = (sraw + 1023) & ~1023u;

    const int tid  = threadIdx.x;
    const int lane = tid & 31;
    const int wid  = tid >> 5;
    const int wr   = wid >> 2;
    const int wc   = wid & 3;

    // loader: thread -> (row r, 64B half h)
    const int r = tid >> 1;
    const int h = (tid & 1) * 64;

    const char* aRowH = (const char*)(Ah + (size_t)z * sA + (size_t)(row0 + r) * K) + h;
    const char* aRowL = (const char*)(Al + (size_t)z * sA + (size_t)(row0 + r) * K) + h;
    const char* bRowH = (const char*)(Bh + (size_t)z * sB + (size_t)(n0 + r) * K) + h;
    const char* bRowL = (const char*)(Bl + (size_t)z * sB + (size_t)(n0 + r) * K) + h;

    uint32_t swo[4];
    #pragma unroll
    for (int i = 0; i < 4; i++) swo[i] = sw128((uint32_t)r * 128u + h + i * 16);

    float acc[4][4][4];
    #pragma unroll
    for (int a = 0; a < 4; a++)
        #pragma unroll
        for (int b = 0; b < 4; b++)
            #pragma unroll
            for (int cc = 0; cc < 4; cc++) acc[a][b][cc] = 0.0f;

    const int nch = K / 64;
    const int T   = 3 * nch;

    const char* aPtr = aRowH;
    const char* bPtr = bRowH;
    int cIss = 0, segIss = 0, bufIss = 0;

    auto issue_one = [&]() {
        uint32_t sa = sb + bufIss * STAGE_B;
        #pragma unroll
        for (int i = 0; i < 4; i++) {
            cp16(sa + swo[i], aPtr + i * 16);
            cp16(sa + 16384 + swo[i], bPtr + i * 16);
        }
        cp_commit();
        aPtr += 128; bPtr += 128;
        bufIss = (bufIss == NSTAGE - 1) ? 0 : bufIss + 1;
        if (++cIss == nch) {
            cIss = 0; segIss++;
            if (segIss == 1)      { aPtr = aRowH; bPtr = bRowL; }
            else if (segIss == 2) { aPtr = aRowL; bPtr = bRowH; }
        }
    };

    issue_one();
    issue_one();

    int bufC = 0;
    for (int t = 0; t < T; t++) {
        if (t + 2 < T)      { issue_one(); cp_wait<2>(); }
        else if (t + 1 < T) { cp_wait<1>(); }
        else                { cp_wait<0>(); }
        __syncthreads();

        const uint32_t aBase = sb + bufC * STAGE_B;
        const uint32_t bBase = aBase + 16384;

        #pragma unroll
        for (int kk = 0; kk < 4; kk++) {
            uint32_t af[4][4];
            #pragma unroll
            for (int mi = 0; mi < 4; mi++) {
                uint32_t row  = wr * 64 + mi * 16 + (lane & 15);
                uint32_t colb = kk * 32 + ((lane >> 4) << 4);
                ldm4(aBase + sw128(row * 128u + colb), af[mi][0], af[mi][1], af[mi][2], af[mi][3]);
            }
            uint32_t bf[2][4];
            #pragma unroll
            for (int ni = 0; ni < 2; ni++) {
                uint32_t q    = lane >> 3;
                uint32_t row  = wc * 32 + ni * 16 + ((q >> 1) << 3) + (lane & 7);
                uint32_t colb = kk * 32 + ((q & 1) << 4);
                ldm4(bBase + sw128(row * 128u + colb), bf[ni][0], bf[ni][1], bf[ni][2], bf[ni][3]);
            }
            #pragma unroll
            for (int mi = 0; mi < 4; mi++)
                #pragma unroll
                for (int n8 = 0; n8 < 4; n8++) {
                    uint32_t b0 = bf[n8 >> 1][(n8 & 1) * 2 + 0];
                    uint32_t b1 = bf[n8 >> 1][(n8 & 1) * 2 + 1];
                    mma16816(acc[mi][n8], af[mi][0], af[mi][1], af[mi][2], af[mi][3], b0, b1);
                }
        }
        __syncthreads();
        bufC = (bufC == NSTAGE - 1) ? 0 : bufC + 1;
    }

    // ---- epilogue
    const int g  = lane >> 2;
    const int tg = lane & 3;
    const int len = (MODE == 1) ? g_lens[z] : 0;

    #pragma unroll
    for (int mi = 0; mi < 4; mi++) {
        const int rA = row0 + wr * 64 + mi * 16 + g;
        const int rB = rA + 8;
        #pragma unroll
        for (int n8 = 0; n8 < 4; n8++) {
            const int col = n0 + wc * 32 + n8 * 8 + tg * 2;
            float v0 = acc[mi][n8][0], v1 = acc[mi][n8][1];
            float v2 = acc[mi][n8][2], v3 = acc[mi][n8][3];
            if (MODE == 0) {
                float* Cz = C + (size_t)z * sC;
                *(float2*)(Cz + (size_t)rA * ldc + col) = make_float2(v0, v1);
                *(float2*)(Cz + (size_t)rB * ldc + col) = make_float2(v2, v3);
            } else if (MODE == 1) {
                float* Cz = C + (size_t)z * sC;
                bool okA = rA < len, okB = rB < len;
                *(float2*)(Cz + (size_t)rA * ldc + col) =
                    make_float2(okA ? v0 * scale : -1e9f, okA ? v1 * scale : -1e9f);
                *(float2*)(Cz + (size_t)rB * ldc + col) =
                    make_float2(okB ? v2 * scale : -1e9f, okB ? v3 * scale : -1e9f);
            } else {
                __nv_bfloat16 h0 = __float2bfloat16(v0), h1 = __float2bfloat16(v1);
                __nv_bfloat16 h2 = __float2bfloat16(v2), h3 = __float2bfloat16(v3);
                __nv_bfloat16 l0 = __float2bfloat16(v0 - __bfloat162float(h0));
                __nv_bfloat16 l1 = __float2bfloat16(v1 - __bfloat162float(h1));
                __nv_bfloat16 l2 = __float2bfloat16(v2 - __bfloat162float(h2));
                __nv_bfloat16 l3 = __float2bfloat16(v3 - __bfloat162float(h3));
                *(uint32_t*)(Poh + (size_t)rA * ldc + col) = pack_bf2(h0, h1);
                *(uint32_t*)(Poh + (size_t)rB * ldc + col) = pack_bf2(h2, h3);
                *(uint32_t*)(Pol + (size_t)rA * ldc + col) = pack_bf2(l0, l1);
                *(uint32_t*)(Pol + (size_t)rB * ldc + col) = pack_bf2(l2, l3);
            }
        }
    }
}

// ---------------------------------------------------------------------------
// Row softmax over Ln=2048, in place + hi/lo bf16 plane outputs.
// Masked rows (q >= len): write exact uniform 1/2048 without reading scores.
// ---------------------------------------------------------------------------
__global__ __launch_bounds__(256)
void softmax_kernel(float* __restrict__ attn, __nv_bfloat16* __restrict__ Ph,
                    __nv_bfloat16* __restrict__ Pl) {
    const size_t row = blockIdx.x;
    const int b  = (int)(row >> 11);
    const int ql = (int)(row & (Ln - 1));
    float* p = attn + row * Ln;
    const int t = threadIdx.x;

    if (ql >= g_lens[b]) {
        const float u = 1.0f / 2048.0f;                      // exact 2^-11
        const unsigned short uh = __bfloat16_as_ushort(__float2bfloat16(u));
        float4 uv = make_float4(u, u, u, u);
        ((float4*)p)[t * 2]     = uv;
        ((float4*)p)[t * 2 + 1] = uv;
        ushort4 us = make_ushort4(uh, uh, uh, uh);
        ushort4 zs = make_ushort4(0, 0, 0, 0);
        __nv_bfloat16* ph = Ph + row * Ln + t * 8;
        __nv_bfloat16* pl = Pl + row * Ln + t * 8;
        *(ushort4*)(ph) = us; *(ushort4*)(ph + 4) = us;
        *(ushort4*)(pl) = zs; *(ushort4*)(pl + 4) = zs;
        return;
    }

    float4 va = ((const float4*)p)[t * 2];
    float4 vb = ((const float4*)p)[t * 2 + 1];
    float v[8] = {va.x, va.y, va.z, va.w, vb.x, vb.y, vb.z, vb.w};

    float m = v[0];
    #pragma unroll
    for (int i = 1; i < 8; i++) m = fmaxf(m, v[i]);

    __shared__ float red[256];
    red[t] = m;
    __syncthreads();
    #pragma unroll
    for (int s = 128; s > 0; s >>= 1) {
        if (t < s) red[t] = fmaxf(red[t], red[t + s]);
        __syncthreads();
    }
    m = red[0];
    __syncthreads();

    float sum = 0.0f;
    #pragma unroll
    for (int i = 0; i < 8; i++) {
        v[i] = expf(v[i] - m);
        sum += v[i];
    }
    red[t] = sum;
    __syncthreads();
    #pragma unroll
    for (int s = 128; s > 0; s >>= 1) {
        if (t < s) red[t] += red[t + s];
        __syncthreads();
    }
    const float inv = 1.0f / red[0];

    unsigned short hb[8], lb[8];
    #pragma unroll
    for (int i = 0; i < 8; i++) {
        v[i] *= inv;
        __nv_bfloat16 hbf = __float2bfloat16(v[i]);
        float hf = __bfloat162float(hbf);
        __nv_bfloat16 lbf = __float2bfloat16(v[i] - hf);
        hb[i] = __bfloat16_as_ushort(hbf);
        lb[i] = __bfloat16_as_ushort(lbf);
    }
    ((float4*)p)[t * 2]     = make_float4(v[0], v[1], v[2], v[3]);
    ((float4*)p)[t * 2 + 1] = make_float4(v[4], v[5], v[6], v[7]);
    __nv_bfloat16* ph = Ph + row * Ln + t * 8;
    __nv_bfloat16* pl = Pl + row * Ln + t * 8;
    *(ushort4*)(ph)     = make_ushort4(hb[0], hb[1], hb[2], hb[3]);
    *(ushort4*)(ph + 4) = make_ushort4(hb[4], hb[5], hb[6], hb[7]);
    *(ushort4*)(pl)     = make_ushort4(lb[0], lb[1], lb[2], lb[3]);
    *(ushort4*)(pl + 4) = make_ushort4(lb[4], lb[5], lb[6], lb[7]);
}

// ---------------------------------------------------------------------------
// kernel_launch
// ---------------------------------------------------------------------------
extern "C" void kernel_launch(void* const* d_in, const int* in_sizes, int n_in,
                              void* d_out, int out_size) {
    const float* X  = (const float*)d_in[0];
    const void*  lens_raw = d_in[1];
    const float* O  = (const float*)d_in[2];
    const float* Wk = (const float*)d_in[3];
    const float* Wv = (const float*)d_in[4];
    const float* Wq = (const float*)d_in[5];

    const long long CTX = (long long)Bn * Ln * Dn;
    const long long ATT = (long long)Bn * Ln * Ln;

    float *vf, *ctx_s, *attn_s, *vm;
    __nv_bfloat16 *Xh, *Xl, *Oh, *Ol, *Wqh, *Wql, *Wkh, *Wkl, *Wvh, *Wvl;
    __nv_bfloat16 *Qh, *Ql, *Kh, *Kl, *Vth, *Vtl, *Ph, *Pl;
    cudaGetSymbolAddress((void**)&vf, g_vf);
    cudaGetSymbolAddress((void**)&ctx_s, g_ctx_scratch);
    cudaGetSymbolAddress((void**)&attn_s, g_attn_scratch);
    cudaGetSymbolAddress((void**)&vm, g_vmean);
    cudaGetSymbolAddress((void**)&Xh, g_Xh);  cudaGetSymbolAddress((void**)&Xl, g_Xl);
    cudaGetSymbolAddress((void**)&Oh, g_Oh);  cudaGetSymbolAddress((void**)&Ol, g_Ol);
    cudaGetSymbolAddress((void**)&Wqh, g_Wqh); cudaGetSymbolAddress((void**)&Wql, g_Wql);
    cudaGetSymbolAddress((void**)&Wkh, g_Wkh); cudaGetSymbolAddress((void**)&Wkl, g_Wkl);
    cudaGetSymbolAddress((void**)&Wvh, g_Wvh); cudaGetSymbolAddress((void**)&Wvl, g_Wvl);
    cudaGetSymbolAddress((void**)&Qh, g_Qh);  cudaGetSymbolAddress((void**)&Ql, g_Ql);
    cudaGetSymbolAddress((void**)&Kh, g_Kh);  cudaGetSymbolAddress((void**)&Kl, g_Kl);
    cudaGetSymbolAddress((void**)&Vth, g_Vth); cudaGetSymbolAddress((void**)&Vtl, g_Vtl);
    cudaGetSymbolAddress((void**)&Ph, g_Ph);  cudaGetSymbolAddress((void**)&Pl, g_Pl);

    float* ctx;
    float* attn;
    if ((long long)out_size >= CTX + ATT) {
        ctx  = (float*)d_out;
        attn = (float*)d_out + CTX;
    } else if ((long long)out_size == ATT) {
        attn = (float*)d_out;
        ctx  = ctx_s;
    } else {
        ctx  = (float*)d_out;
        attn = attn_s;
    }

    cudaFuncSetAttribute(hmma_gemm<0>, cudaFuncAttributeMaxDynamicSharedMemorySize, SMEM_REQ);
    cudaFuncSetAttribute(hmma_gemm<1>, cudaFuncAttributeMaxDynamicSharedMemorySize, SMEM_REQ);
    cudaFuncSetAttribute(hmma_gemm<2>, cudaFuncAttributeMaxDynamicSharedMemorySize, SMEM_REQ);

    prep_lens_kernel<<<1, 32>>>(lens_raw);

    // hi/lo expansions of raw inputs
    {
        long long t4 = (long long)M_ALL * Dn / 4;
        int blocks = (int)((t4 + 255) / 256);
        expand2_kernel<<<blocks, 256>>>(X, Xh, Xl, t4);
        expand2_kernel<<<blocks, 256>>>(O, Oh, Ol, t4);
        long long w4 = (long long)Dn * Dn / 4;
        int wb = (int)((w4 + 255) / 256);
        expand2_kernel<<<wb, 256>>>(Wq, Wqh, Wql, w4);
        expand2_kernel<<<wb, 256>>>(Wk, Wkh, Wkl, w4);
        expand2_kernel<<<wb, 256>>>(Wv, Wvh, Wvl, w4);
    }

    // Projections: M=16384, N=1024, K=1024
    {
        dim3 grid(Dn / 128, M_ALL / 128, 1);
        // q: bf16 hi/lo planes out; skip fully-masked row tiles (skipMode 2)
        hmma_gemm<2><<<grid, 256, SMEM_REQ>>>(Oh, Ol, Wqh, Wql, nullptr, Qh, Ql,
                                              Dn, Dn, 0, 0, 0, 1.0f, 2);
        // k, v: all key rows needed (mask is query-axis only)
        hmma_gemm<2><<<grid, 256, SMEM_REQ>>>(Xh, Xl, Wkh, Wkl, nullptr, Kh, Kl,
                                              Dn, Dn, 0, 0, 0, 1.0f, 0);
        hmma_gemm<0><<<grid, 256, SMEM_REQ>>>(Xh, Xl, Wvh, Wvl, vf, nullptr, nullptr,
                                              Dn, Dn, 0, 0, 0, 1.0f, 0);
    }

    // V transpose + split; per-batch V column means
    vtrans_kernel<<<dim3(Dn / 32, M_ALL / 32), 256>>>(vf, Vth, Vtl);
    vmean_kernel<<<dim3(Dn / 256, Bn), 256>>>(vf, vm);

    // Scores: per batch M=N=2048, K=1024; scale + query-row mask; skip masked tiles
    {
        dim3 grid(Ln / 128, Ln / 128, Bn);
        hmma_gemm<1><<<grid, 256, SMEM_REQ>>>(Qh, Ql, Kh, Kl, attn, nullptr, nullptr,
                                              Dn, Ln, (long long)Ln * Dn, (long long)Ln * Dn,
                                              (long long)Ln * Ln, 0.03125f, 1);
    }

    // Softmax in place + P hi/lo planes (uniform fill for masked rows)
    softmax_kernel<<<Bn * Ln, 256>>>(attn, Ph, Pl);

    // Context: per batch M=2048, N=1024, K=2048; skip masked tiles
    {
        dim3 grid(Dn / 128, Ln / 128, Bn);
        hmma_gemm<0><<<grid, 256, SMEM_REQ>>>(Ph, Pl, Vth, Vtl, ctx, nullptr, nullptr,
                                              Ln, Dn, (long long)Ln * Ln, (long long)Dn * Ln,
                                              (long long)Ln * Dn, 1.0f, 1);
    }

    // Masked ctx rows = per-batch V mean
    fill_masked_kernel<<<dim3(Dn / 256, Ln, Bn), 256>>>(vm, ctx);
}

// round 6
// speedup vs baseline: 4.4006x; 1.2895x over previous
#include <cuda_runtime.h>
#include <cuda_fp16.h>
#include <math.h>
#include <stdint.h>

#define Bn 8
#define Ln 2048
#define Dn 1024
#define M_ALL (Bn * Ln)   // 16384

// ---------------------------------------------------------------------------
// Device scratch (allocation-free rule -> __device__ globals)
// ---------------------------------------------------------------------------
__device__ float g_ctx_scratch[(size_t)M_ALL * Dn];
__device__ float g_attn_scratch[(size_t)Bn * Ln * Ln];
__device__ float g_vmean[(size_t)Bn * Dn];
__device__ float g_xmean[(size_t)Bn * Dn];
__device__ int   g_lens[Bn];

// fp16 hi/lo planes
__device__ __half g_Xh[(size_t)M_ALL * Dn];
__device__ __half g_Xl[(size_t)M_ALL * Dn];
__device__ __half g_Oh[(size_t)M_ALL * Dn];
__device__ __half g_Ol[(size_t)M_ALL * Dn];
__device__ __half g_Wvh[(size_t)Dn * Dn];
__device__ __half g_Wvl[(size_t)Dn * Dn];
__device__ __half g_WqTh[(size_t)Dn * Dn];
__device__ __half g_WqTl[(size_t)Dn * Dn];
__device__ __half g_WkTh[(size_t)Dn * Dn];
__device__ __half g_WkTl[(size_t)Dn * Dn];
__device__ __half g_GTh[(size_t)Dn * Dn];
__device__ __half g_GTl[(size_t)Dn * Dn];
__device__ __half g_QGh[(size_t)M_ALL * Dn];
__device__ __half g_QGl[(size_t)M_ALL * Dn];
__device__ __half g_XTh[(size_t)Bn * Dn * Ln];
__device__ __half g_XTl[(size_t)Bn * Dn * Ln];
__device__ __half g_Ph[(size_t)M_ALL * Ln];
__device__ __half g_Pl[(size_t)M_ALL * Ln];
__device__ __half g_PXh[(size_t)M_ALL * Dn];
__device__ __half g_PXl[(size_t)M_ALL * Dn];

// ---------------------------------------------------------------------------
// lens dtype sniffing (int64 vs int32)
// ---------------------------------------------------------------------------
__global__ void prep_lens_kernel(const void* lensraw) {
    if (threadIdx.x == 0 && blockIdx.x == 0) {
        const int* a32 = (const int*)lensraw;
        bool is64 = true;
        #pragma unroll
        for (int i = 0; i < 4; i++) {
            int lo = a32[2 * i], hi = a32[2 * i + 1];
            if (hi != 0 || lo < 1 || lo > Ln) { is64 = false; break; }
        }
        if (is64) {
            const long long* a64 = (const long long*)lensraw;
            for (int i = 0; i < Bn; i++) g_lens[i] = (int)a64[i];
        } else {
            for (int i = 0; i < Bn; i++) g_lens[i] = a32[i];
        }
    }
}

// ---------------------------------------------------------------------------
// fp32 -> (hi, lo) fp16 planes, flat
// ---------------------------------------------------------------------------
__global__ __launch_bounds__(256)
void expand2_kernel(const float* __restrict__ src, __half* __restrict__ dh,
                    __half* __restrict__ dl, long long total4) {
    long long i = (long long)blockIdx.x * blockDim.x + threadIdx.x;
    if (i >= total4) return;
    float4 v = *(const float4*)(src + i * 4);
    float vv[4] = {v.x, v.y, v.z, v.w};
    unsigned short hb[4], lb[4];
    #pragma unroll
    for (int j = 0; j < 4; j++) {
        __half hbf = __float2half_rn(vv[j]);
        float hf = __half2float(hbf);
        __half lbf = __float2half_rn(vv[j] - hf);
        hb[j] = __half_as_ushort(hbf);
        lb[j] = __half_as_ushort(lbf);
    }
    *(ushort4*)(dh + i * 4) = make_ushort4(hb[0], hb[1], hb[2], hb[3]);
    *(ushort4*)(dl + i * 4) = make_ushort4(lb[0], lb[1], lb[2], lb[3]);
}

// ---------------------------------------------------------------------------
// Transpose fp32 [R,C] -> fp16 hi/lo planes [C,R]; batched via blockIdx.z.
// ---------------------------------------------------------------------------
__global__ __launch_bounds__(256)
void trans_kernel(const float* __restrict__ src, __half* __restrict__ oh,
                  __half* __restrict__ ol, int R, int C) {
    __shared__ float tile[32][33];
    size_t bo = (size_t)blockIdx.z * R * C;
    src += bo; oh += bo; ol += bo;
    int c0 = blockIdx.x * 32;
    int r0 = blockIdx.y * 32;
    int tx = threadIdx.x & 31;
    int ty = threadIdx.x >> 5;

    #pragma unroll
    for (int j = 0; j < 4; j++)
        tile[ty + j * 8][tx] = src[(size_t)(r0 + ty + j * 8) * C + c0 + tx];
    __syncthreads();

    #pragma unroll
    for (int j = 0; j < 4; j++) {
        float v = tile[tx][ty + j * 8];
        __half h = __float2half_rn(v);
        __half l = __float2half_rn(v - __half2float(h));
        size_t o = (size_t)(c0 + ty + j * 8) * R + r0 + tx;
        oh[o] = h;
        ol[o] = l;
    }
}

// ---------------------------------------------------------------------------
// xmean[b][d] = (1/2048) * sum_t X[b*Ln+t][d]
// ---------------------------------------------------------------------------
__global__ __launch_bounds__(256)
void xmean_kernel(const float* __restrict__ xf, float* __restrict__ xm) {
    int b = blockIdx.y;
    int d = blockIdx.x * 256 + threadIdx.x;
    const float* p = xf + (size_t)b * Ln * Dn + d;
    float s0 = 0.f, s1 = 0.f, s2 = 0.f, s3 = 0.f;
    for (int t = 0; t < Ln; t += 4) {
        s0 += p[(size_t)(t + 0) * Dn];
        s1 += p[(size_t)(t + 1) * Dn];
        s2 += p[(size_t)(t + 2) * Dn];
        s3 += p[(size_t)(t + 3) * Dn];
    }
    xm[b * Dn + d] = (s0 + s1 + s2 + s3) * (1.0f / 2048.0f);
}

// ---------------------------------------------------------------------------
// vmean[b][e] = sum_d xmean[b][d] * Wv[e][d]   (fp32, exact path)
// one warp per output element
// ---------------------------------------------------------------------------
__global__ __launch_bounds__(256)
void vmeanw_kernel(const float* __restrict__ xm, const float* __restrict__ Wv,
                   float* __restrict__ vm) {
    int b = blockIdx.y;
    int e = blockIdx.x * 8 + (threadIdx.x >> 5);
    int lane = threadIdx.x & 31;
    const float* xr = xm + b * Dn;
    const float* wr = Wv + (size_t)e * Dn;
    float s = 0.f;
    for (int d = lane; d < Dn; d += 32) s += xr[d] * wr[d];
    #pragma unroll
    for (int o = 16; o > 0; o >>= 1) s += __shfl_down_sync(0xffffffffu, s, o);
    if (lane == 0) vm[b * Dn + e] = s;
}

// ---------------------------------------------------------------------------
// Fill masked ctx rows with vmean
// ---------------------------------------------------------------------------
__global__ __launch_bounds__(256)
void fill_masked_kernel(const float* __restrict__ vm, float* __restrict__ ctx) {
    int b = blockIdx.z;
    int q = blockIdx.y;
    if (q < g_lens[b]) return;
    int d = blockIdx.x * 256 + threadIdx.x;
    ctx[((size_t)b * Ln + q) * Dn + d] = vm[b * Dn + d];
}

// ---------------------------------------------------------------------------
// HMMA GEMM core (mma.sync m16n8k16 fp16, fp32 accum), NT.
// 3 K-segments over hi/lo planes: (Ah,Bh), (Ah,Bl), (Al,Bh).
// BM=BN=128, BK=64, 3-stage cp.async, 8 warps 2x4, warp tile 64x32.
// MODE 0: fp32 C. MODE 1: scale+mask fp32 C. MODE 2: write hi/lo fp16 planes.
// skipMode 1: skip tile if local row0 >= lens[z]
// skipMode 2: skip tile if (row0 & 2047) >= lens[row0 >> 11]
// ---------------------------------------------------------------------------
__device__ __forceinline__ uint32_t sw128(uint32_t x) { return x ^ ((x >> 3) & 0x70); }

#define STAGE_B 32768
#define NSTAGE  3
#define SMEM_REQ (1024 + NSTAGE * STAGE_B)

__device__ __forceinline__ void cp16(uint32_t saddr, const void* gaddr) {
    asm volatile("cp.async.cg.shared.global [%0], [%1], 16;" :: "r"(saddr), "l"(gaddr));
}
__device__ __forceinline__ void cp_commit() {
    asm volatile("cp.async.commit_group;" ::: "memory");
}
template <int N> __device__ __forceinline__ void cp_wait() {
    asm volatile("cp.async.wait_group %0;" :: "n"(N) : "memory");
}
__device__ __forceinline__ void ldm4(uint32_t addr, uint32_t& r0, uint32_t& r1,
                                     uint32_t& r2, uint32_t& r3) {
    asm volatile("ldmatrix.sync.aligned.m8n8.x4.shared.b16 {%0,%1,%2,%3}, [%4];"
                 : "=r"(r0), "=r"(r1), "=r"(r2), "=r"(r3) : "r"(addr));
}
__device__ __forceinline__ void mma16816(float* c, uint32_t a0, uint32_t a1,
                                         uint32_t a2, uint32_t a3,
                                         uint32_t b0, uint32_t b1) {
    asm volatile(
        "mma.sync.aligned.m16n8k16.row.col.f32.f16.f16.f32 "
        "{%0,%1,%2,%3},{%4,%5,%6,%7},{%8,%9},{%0,%1,%2,%3};"
        : "+f"(c[0]), "+f"(c[1]), "+f"(c[2]), "+f"(c[3])
        : "r"(a0), "r"(a1), "r"(a2), "r"(a3), "r"(b0), "r"(b1));
}
__device__ __forceinline__ uint32_t pack_h2(__half a, __half b) {
    return (uint32_t)__half_as_ushort(a) | ((uint32_t)__half_as_ushort(b) << 16);
}

template <int MODE>
__global__ __launch_bounds__(256, 2)
void hmma_gemm(const __half* __restrict__ Ah, const __half* __restrict__ Al,
               const __half* __restrict__ Bh, const __half* __restrict__ Bl,
               float* __restrict__ C,
               __half* __restrict__ Poh, __half* __restrict__ Pol,
               int K, int ldc,
               long long sA, long long sB, long long sC, float scale, int skipMode) {
    const int z    = blockIdx.z;
    const int row0 = blockIdx.y * 128;
    const int n0   = blockIdx.x * 128;

    if (skipMode == 1) {
        if (row0 >= g_lens[z]) return;
    } else if (skipMode == 2) {
        if ((row0 & (Ln - 1)) >= g_lens[row0 >> 11]) return;
    }

    extern __shared__ char dsm[];
    uint32_t sraw = (uint32_t)__cvta_generic_to_shared(dsm);
    uint32_t sb   = (sraw + 1023) & ~1023u;

    const int tid  = threadIdx.x;
    const int lane = tid & 31;
    const int wid  = tid >> 5;
    const int wr   = wid >> 2;
    const int wc   = wid & 3;

    const int r = tid >> 1;
    const int h = (tid & 1) * 64;

    const char* aRowH = (const char*)(Ah + (size_t)z * sA + (size_t)(row0 + r) * K) + h;
    const char* aRowL = (const char*)(Al + (size_t)z * sA + (size_t)(row0 + r) * K) + h;
    const char* bRowH = (const char*)(Bh + (size_t)z * sB + (size_t)(n0 + r) * K) + h;
    const char* bRowL = (const char*)(Bl + (size_t)z * sB + (size_t)(n0 + r) * K) + h;

    uint32_t swo[4];
    #pragma unroll
    for (int i = 0; i < 4; i++) swo[i] = sw128((uint32_t)r * 128u + h + i * 16);

    float acc[4][4][4];
    #pragma unroll
    for (int a = 0; a < 4; a++)
        #pragma unroll
        for (int b = 0; b < 4; b++)
            #pragma unroll
            for (int cc = 0; cc < 4; cc++) acc[a][b][cc] = 0.0f;

    const int nch = K / 64;
    const int T   = 3 * nch;

    const char* aPtr = aRowH;
    const char* bPtr = bRowH;
    int cIss = 0, segIss = 0, bufIss = 0;

    auto issue_one = [&]() {
        uint32_t sa = sb + bufIss * STAGE_B;
        #pragma unroll
        for (int i = 0; i < 4; i++) {
            cp16(sa + swo[i], aPtr + i * 16);
            cp16(sa + 16384 + swo[i], bPtr + i * 16);
        }
        cp_commit();
        aPtr += 128; bPtr += 128;
        bufIss = (bufIss == NSTAGE - 1) ? 0 : bufIss + 1;
        if (++cIss == nch) {
            cIss = 0; segIss++;
            if (segIss == 1)      { aPtr = aRowH; bPtr = bRowL; }
            else if (segIss == 2) { aPtr = aRowL; bPtr = bRowH; }
        }
    };

    issue_one();
    issue_one();

    int bufC = 0;
    for (int t = 0; t < T; t++) {
        if (t + 2 < T)      { issue_one(); cp_wait<2>(); }
        else if (t + 1 < T) { cp_wait<1>(); }
        else                { cp_wait<0>(); }
        __syncthreads();

        const uint32_t aBase = sb + bufC * STAGE_B;
        const uint32_t bBase = aBase + 16384;

        #pragma unroll
        for (int kk = 0; kk < 4; kk++) {
            uint32_t af[4][4];
            #pragma unroll
            for (int mi = 0; mi < 4; mi++) {
                uint32_t row  = wr * 64 + mi * 16 + (lane & 15);
                uint32_t colb = kk * 32 + ((lane >> 4) << 4);
                ldm4(aBase + sw128(row * 128u + colb), af[mi][0], af[mi][1], af[mi][2], af[mi][3]);
            }
            uint32_t bf[2][4];
            #pragma unroll
            for (int ni = 0; ni < 2; ni++) {
                uint32_t q    = lane >> 3;
                uint32_t row  = wc * 32 + ni * 16 + ((q >> 1) << 3) + (lane & 7);
                uint32_t colb = kk * 32 + ((q & 1) << 4);
                ldm4(bBase + sw128(row * 128u + colb), bf[ni][0], bf[ni][1], bf[ni][2], bf[ni][3]);
            }
            #pragma unroll
            for (int mi = 0; mi < 4; mi++)
                #pragma unroll
                for (int n8 = 0; n8 < 4; n8++) {
                    uint32_t b0 = bf[n8 >> 1][(n8 & 1) * 2 + 0];
                    uint32_t b1 = bf[n8 >> 1][(n8 & 1) * 2 + 1];
                    mma16816(acc[mi][n8], af[mi][0], af[mi][1], af[mi][2], af[mi][3], b0, b1);
                }
        }
        __syncthreads();
        bufC = (bufC == NSTAGE - 1) ? 0 : bufC + 1;
    }

    // ---- epilogue
    const int g  = lane >> 2;
    const int tg = lane & 3;
    const int len = (MODE == 1) ? g_lens[z] : 0;

    #pragma unroll
    for (int mi = 0; mi < 4; mi++) {
        const int rA = row0 + wr * 64 + mi * 16 + g;
        const int rB = rA + 8;
        #pragma unroll
        for (int n8 = 0; n8 < 4; n8++) {
            const int col = n0 + wc * 32 + n8 * 8 + tg * 2;
            float v0 = acc[mi][n8][0], v1 = acc[mi][n8][1];
            float v2 = acc[mi][n8][2], v3 = acc[mi][n8][3];
            if (MODE == 0) {
                float* Cz = C + (size_t)z * sC;
                *(float2*)(Cz + (size_t)rA * ldc + col) = make_float2(v0, v1);
                *(float2*)(Cz + (size_t)rB * ldc + col) = make_float2(v2, v3);
            } else if (MODE == 1) {
                float* Cz = C + (size_t)z * sC;
                bool okA = rA < len, okB = rB < len;
                *(float2*)(Cz + (size_t)rA * ldc + col) =
                    make_float2(okA ? v0 * scale : -1e9f, okA ? v1 * scale : -1e9f);
                *(float2*)(Cz + (size_t)rB * ldc + col) =
                    make_float2(okB ? v2 * scale : -1e9f, okB ? v3 * scale : -1e9f);
            } else {
                __half* PohZ = Poh + (size_t)z * sC;
                __half* PolZ = Pol + (size_t)z * sC;
                __half h0 = __float2half_rn(v0), h1 = __float2half_rn(v1);
                __half h2 = __float2half_rn(v2), h3 = __float2half_rn(v3);
                __half l0 = __float2half_rn(v0 - __half2float(h0));
                __half l1 = __float2half_rn(v1 - __half2float(h1));
                __half l2 = __float2half_rn(v2 - __half2float(h2));
                __half l3 = __float2half_rn(v3 - __half2float(h3));
                *(uint32_t*)(PohZ + (size_t)rA * ldc + col) = pack_h2(h0, h1);
                *(uint32_t*)(PohZ + (size_t)rB * ldc + col) = pack_h2(h2, h3);
                *(uint32_t*)(PolZ + (size_t)rA * ldc + col) = pack_h2(l0, l1);
                *(uint32_t*)(PolZ + (size_t)rB * ldc + col) = pack_h2(l2, l3);
            }
        }
    }
}

// ---------------------------------------------------------------------------
// Row softmax over Ln=2048, in place + hi/lo fp16 plane outputs.
// Masked rows (q >= len): exact uniform 1/2048, no reads.
// ---------------------------------------------------------------------------
__global__ __launch_bounds__(256)
void softmax_kernel(float* __restrict__ attn, __half* __restrict__ Ph,
                    __half* __restrict__ Pl) {
    const size_t row = blockIdx.x;
    const int b  = (int)(row >> 11);
    const int ql = (int)(row & (Ln - 1));
    float* p = attn + row * Ln;
    const int t = threadIdx.x;

    if (ql >= g_lens[b]) {
        const float u = 1.0f / 2048.0f;   // exact 2^-11 in fp32 and fp16
        const unsigned short uh = __half_as_ushort(__float2half_rn(u));
        float4 uv = make_float4(u, u, u, u);
        ((float4*)p)[t * 2]     = uv;
        ((float4*)p)[t * 2 + 1] = uv;
        ushort4 us = make_ushort4(uh, uh, uh, uh);
        ushort4 zs = make_ushort4(0, 0, 0, 0);
        __half* ph = Ph + row * Ln + t * 8;
        __half* pl = Pl + row * Ln + t * 8;
        *(ushort4*)(ph) = us; *(ushort4*)(ph + 4) = us;
        *(ushort4*)(pl) = zs; *(ushort4*)(pl + 4) = zs;
        return;
    }

    float4 va = ((const float4*)p)[t * 2];
    float4 vb = ((const float4*)p)[t * 2 + 1];
    float v[8] = {va.x, va.y, va.z, va.w, vb.x, vb.y, vb.z, vb.w};

    float m = v[0];
    #pragma unroll
    for (int i = 1; i < 8; i++) m = fmaxf(m, v[i]);

    __shared__ float red[256];
    red[t] = m;
    __syncthreads();
    #pragma unroll
    for (int s = 128; s > 0; s >>= 1) {
        if (t < s) red[t] = fmaxf(red[t], red[t + s]);
        __syncthreads();
    }
    m = red[0];
    __syncthreads();

    float sum = 0.0f;
    #pragma unroll
    for (int i = 0; i < 8; i++) {
        v[i] = expf(v[i] - m);
        sum += v[i];
    }
    red[t] = sum;
    __syncthreads();
    #pragma unroll
    for (int s = 128; s > 0; s >>= 1) {
        if (t < s) red[t] += red[t + s];
        __syncthreads();
    }
    const float inv = 1.0f / red[0];

    unsigned short hb[8], lb[8];
    #pragma unroll
    for (int i = 0; i < 8; i++) {
        v[i] *= inv;
        __half hbf = __float2half_rn(v[i]);
        float hf = __half2float(hbf);
        __half lbf = __float2half_rn(v[i] - hf);
        hb[i] = __half_as_ushort(hbf);
        lb[i] = __half_as_ushort(lbf);
    }
    ((float4*)p)[t * 2]     = make_float4(v[0], v[1], v[2], v[3]);
    ((float4*)p)[t * 2 + 1] = make_float4(v[4], v[5], v[6], v[7]);
    __half* ph = Ph + row * Ln + t * 8;
    __half* pl = Pl + row * Ln + t * 8;
    *(ushort4*)(ph)     = make_ushort4(hb[0], hb[1], hb[2], hb[3]);
    *(ushort4*)(ph + 4) = make_ushort4(hb[4], hb[5], hb[6], hb[7]);
    *(ushort4*)(pl)     = make_ushort4(lb[0], lb[1], lb[2], lb[3]);
    *(ushort4*)(pl + 4) = make_ushort4(lb[4], lb[5], lb[6], lb[7]);
}

// ---------------------------------------------------------------------------
// kernel_launch
// ---------------------------------------------------------------------------
extern "C" void kernel_launch(void* const* d_in, const int* in_sizes, int n_in,
                              void* d_out, int out_size) {
    const float* X  = (const float*)d_in[0];
    const void*  lens_raw = d_in[1];
    const float* O  = (const float*)d_in[2];
    const float* Wk = (const float*)d_in[3];
    const float* Wv = (const float*)d_in[4];
    const float* Wq = (const float*)d_in[5];

    const long long CTX = (long long)Bn * Ln * Dn;
    const long long ATT = (long long)Bn * Ln * Ln;

    float *ctx_s, *attn_s, *vm, *xm;
    __half *Xh, *Xl, *Oh, *Ol, *Wvh, *Wvl, *WqTh, *WqTl, *WkTh, *WkTl;
    __half *GTh, *GTl, *QGh, *QGl, *XTh, *XTl, *Ph, *Pl, *PXh, *PXl;
    cudaGetSymbolAddress((void**)&ctx_s, g_ctx_scratch);
    cudaGetSymbolAddress((void**)&attn_s, g_attn_scratch);
    cudaGetSymbolAddress((void**)&vm, g_vmean);
    cudaGetSymbolAddress((void**)&xm, g_xmean);
    cudaGetSymbolAddress((void**)&Xh, g_Xh);   cudaGetSymbolAddress((void**)&Xl, g_Xl);
    cudaGetSymbolAddress((void**)&Oh, g_Oh);   cudaGetSymbolAddress((void**)&Ol, g_Ol);
    cudaGetSymbolAddress((void**)&Wvh, g_Wvh); cudaGetSymbolAddress((void**)&Wvl, g_Wvl);
    cudaGetSymbolAddress((void**)&WqTh, g_WqTh); cudaGetSymbolAddress((void**)&WqTl, g_WqTl);
    cudaGetSymbolAddress((void**)&WkTh, g_WkTh); cudaGetSymbolAddress((void**)&WkTl, g_WkTl);
    cudaGetSymbolAddress((void**)&GTh, g_GTh); cudaGetSymbolAddress((void**)&GTl, g_GTl);
    cudaGetSymbolAddress((void**)&QGh, g_QGh); cudaGetSymbolAddress((void**)&QGl, g_QGl);
    cudaGetSymbolAddress((void**)&XTh, g_XTh); cudaGetSymbolAddress((void**)&XTl, g_XTl);
    cudaGetSymbolAddress((void**)&Ph, g_Ph);   cudaGetSymbolAddress((void**)&Pl, g_Pl);
    cudaGetSymbolAddress((void**)&PXh, g_PXh); cudaGetSymbolAddress((void**)&PXl, g_PXl);

    float* ctx;
    float* attn;
    if ((long long)out_size >= CTX + ATT) {
        ctx  = (float*)d_out;
        attn = (float*)d_out + CTX;
    } else if ((long long)out_size == ATT) {
        attn = (float*)d_out;
        ctx  = ctx_s;
    } else {
        ctx  = (float*)d_out;
        attn = attn_s;
    }

    cudaFuncSetAttribute(hmma_gemm<0>, cudaFuncAttributeMaxDynamicSharedMemorySize, SMEM_REQ);
    cudaFuncSetAttribute(hmma_gemm<1>, cudaFuncAttributeMaxDynamicSharedMemorySize, SMEM_REQ);
    cudaFuncSetAttribute(hmma_gemm<2>, cudaFuncAttributeMaxDynamicSharedMemorySize, SMEM_REQ);

    prep_lens_kernel<<<1, 32>>>(lens_raw);

    // Expansions + transposes of raw inputs
    {
        long long t4 = (long long)M_ALL * Dn / 4;
        int blocks = (int)((t4 + 255) / 256);
        expand2_kernel<<<blocks, 256>>>(X, Xh, Xl, t4);
        expand2_kernel<<<blocks, 256>>>(O, Oh, Ol, t4);
        long long w4 = (long long)Dn * Dn / 4;
        int wb = (int)((w4 + 255) / 256);
        expand2_kernel<<<wb, 256>>>(Wv, Wvh, Wvl, w4);
        trans_kernel<<<dim3(Dn / 32, Dn / 32, 1), 256>>>(Wq, WqTh, WqTl, Dn, Dn);
        trans_kernel<<<dim3(Dn / 32, Dn / 32, 1), 256>>>(Wk, WkTh, WkTl, Dn, Dn);
        trans_kernel<<<dim3(Dn / 32, Ln / 32, Bn), 256>>>(X, XTh, XTl, Ln, Dn);
    }

    // vmean = (mean_t X) @ Wv^T  (exact fp32 path for masked ctx rows)
    xmean_kernel<<<dim3(Dn / 256, Bn), 256>>>(X, xm);
    vmeanw_kernel<<<dim3(Dn / 8, Bn), 256>>>(xm, Wv, vm);

    // GT = Wk^T @ Wq  (GT[d2][d1] = sum_e Wk[e][d2] Wq[e][d1])
    hmma_gemm<2><<<dim3(Dn / 128, Dn / 128, 1), 256, SMEM_REQ>>>(
        WkTh, WkTl, WqTh, WqTl, nullptr, GTh, GTl, Dn, Dn, 0, 0, 0, 1.0f, 0);

    // QG = O @ G  (QG[l][d2] = sum_d1 O[l][d1] GT[d2][d1]); masked row tiles skipped
    hmma_gemm<2><<<dim3(Dn / 128, M_ALL / 128, 1), 256, SMEM_REQ>>>(
        Oh, Ol, GTh, GTl, nullptr, QGh, QGl, Dn, Dn, 0, 0, 0, 1.0f, 2);

    // scores = QG @ X^T / 32, per batch, query-mask epilogue, masked tiles skipped
    hmma_gemm<1><<<dim3(Ln / 128, Ln / 128, Bn), 256, SMEM_REQ>>>(
        QGh, QGl, Xh, Xl, attn, nullptr, nullptr, Dn, Ln,
        (long long)Ln * Dn, (long long)Ln * Dn, (long long)Ln * Ln, 0.03125f, 1);

    // Softmax in place + P hi/lo planes (uniform fill for masked rows)
    softmax_kernel<<<Bn * Ln, 256>>>(attn, Ph, Pl);

    // PX = P @ X per batch (PX[q][d] = sum_t P[q][t] XT[d][t]); masked tiles skipped
    hmma_gemm<2><<<dim3(Dn / 128, Ln / 128, Bn), 256, SMEM_REQ>>>(
        Ph, Pl, XTh, XTl, nullptr, PXh, PXl, Ln, Dn,
        (long long)Ln * Ln, (long long)Dn * Ln, (long long)Ln * Dn, 1.0f, 1);

    // ctx = PX @ Wv^T; masked tiles skipped
    hmma_gemm<0><<<dim3(Dn / 128, M_ALL / 128, 1), 256, SMEM_REQ>>>(
        PXh, PXl, Wvh, Wvl, ctx, nullptr, nullptr, Dn, Dn, 0, 0, 0, 1.0f, 2);

    // Masked ctx rows = per-batch V mean
    fill_masked_kernel<<<dim3(Dn / 256, Ln, Bn), 256>>>(vm, ctx);
}